// round 1
// baseline (speedup 1.0000x reference)
#include <cuda_runtime.h>
#include <math.h>

#define B_ 2048
#define D_ 512
#define C_ 10000

// ---------- scratch (device globals: alloc-free, capture-safe) ----------
__device__ float g_xn[B_ * D_];            // normalized x
__device__ float g_wn[C_ * D_];            // normalized weight
__device__ float g_wm[B_ * D_];            // normalize(weight_m[label])
__device__ float g_wk[B_ * D_];            // normalize(weight_n[label])
__device__ float g_cos[(size_t)B_ * C_];   // AAM cosine matrix
__device__ float g_q[(size_t)B_ * B_];
__device__ float g_k[(size_t)B_ * B_];
__device__ float g_aam_row[B_];
__device__ float g_expneg[B_];
__device__ float g_nmp[B_];
__device__ float g_cos_apm[B_];
__device__ float g_sin_apm[B_];

// ---------- constants ----------
constexpr float K_S    = 30.0f;
constexpr float K_COSM = 0.9800665778412416f;   // cos(0.2)
constexpr float K_SINM = 0.19866933079506122f;  // sin(0.2)
constexpr float K_TH   = -0.9800665778412416f;  // cos(pi - 0.2)
constexpr float K_MM   = 0.039733866159012244f; // sin(pi-0.2)*0.2
constexpr float K_EPS  = 0.1f;

// ---------- block-wide sum (result broadcast to all threads) ----------
__device__ __forceinline__ float block_sum_all(float v) {
    __shared__ float sh[33];
    int lane = threadIdx.x & 31, wid = threadIdx.x >> 5;
#pragma unroll
    for (int o = 16; o; o >>= 1) v += __shfl_down_sync(0xffffffffu, v, o);
    __syncthreads();                 // protect sh reuse across calls
    if (lane == 0) sh[wid] = v;
    __syncthreads();
    if (threadIdx.x == 0) {
        float s = 0.f;
        int nw = (blockDim.x + 31) >> 5;
        for (int w = 0; w < nw; w++) s += sh[w];
        sh[32] = s;
    }
    __syncthreads();
    return sh[32];
}

// ---------- row L2-normalize (rowlen = 512, 128 threads/row) ----------
__global__ void normalize_rows_kernel(const float* __restrict__ src,
                                      float* __restrict__ dst) {
    int r = blockIdx.x;
    int t = threadIdx.x;  // 0..127, each handles one float4
    const float4 v = *(const float4*)(src + (size_t)r * D_ + t * 4);
    float ss = v.x * v.x + v.y * v.y + v.z * v.z + v.w * v.w;
    float tot = block_sum_all(ss);
    float inv = 1.0f / fmaxf(sqrtf(tot), 1e-12f);
    float4 o = make_float4(v.x * inv, v.y * inv, v.z * inv, v.w * inv);
    *(float4*)(dst + (size_t)r * D_ + t * 4) = o;
}

// ---------- gather weight_m[label], weight_n[label] + normalize ----------
__global__ void gather_normalize_kernel(const float* __restrict__ wm,
                                        const float* __restrict__ wk,
                                        const int* __restrict__ label) {
    int i = blockIdx.x;
    int t = threadIdx.x;
    int c = label[i];
    {
        const float4 v = *(const float4*)(wm + (size_t)c * D_ + t * 4);
        float tot = block_sum_all(v.x * v.x + v.y * v.y + v.z * v.z + v.w * v.w);
        float inv = 1.0f / fmaxf(sqrtf(tot), 1e-12f);
        *(float4*)(g_wm + (size_t)i * D_ + t * 4) =
            make_float4(v.x * inv, v.y * inv, v.z * inv, v.w * inv);
    }
    {
        const float4 v = *(const float4*)(wk + (size_t)c * D_ + t * 4);
        float tot = block_sum_all(v.x * v.x + v.y * v.y + v.z * v.z + v.w * v.w);
        float inv = 1.0f / fmaxf(sqrtf(tot), 1e-12f);
        *(float4*)(g_wk + (size_t)i * D_ + t * 4) =
            make_float4(v.x * inv, v.y * inv, v.z * inv, v.w * inv);
    }
}

// ---------- C[m,n] = sum_k A[m,k]*B[n,k]; A:[M,K] rowmajor, B:[N,K] rowmajor
// 128x128x16 tile, 256 threads, 8x8 microtile. M assumed multiple of 128.
__global__ void __launch_bounds__(256)
gemm_nt_kernel(const float* __restrict__ A, const float* __restrict__ Bm,
               float* __restrict__ Cm, int N, int K) {
    __shared__ float As[16][128];
    __shared__ float Bs[16][128];
    int tid = threadIdx.x;
    int bm = blockIdx.y * 128;
    int bn = blockIdx.x * 128;
    int tx = tid & 15, ty = tid >> 4;
    int lr = tid >> 2;          // 0..63
    int lc = (tid & 3) << 2;    // 0,4,8,12

    float acc[8][8];
#pragma unroll
    for (int i = 0; i < 8; i++)
#pragma unroll
        for (int j = 0; j < 8; j++) acc[i][j] = 0.f;

    for (int k0 = 0; k0 < K; k0 += 16) {
#pragma unroll
        for (int h = 0; h < 2; h++) {
            int r = lr + h * 64;
            float4 v = *(const float4*)(A + (size_t)(bm + r) * K + k0 + lc);
            As[lc + 0][r] = v.x; As[lc + 1][r] = v.y;
            As[lc + 2][r] = v.z; As[lc + 3][r] = v.w;
            int n = bn + r;
            float4 w = make_float4(0.f, 0.f, 0.f, 0.f);
            if (n < N) w = *(const float4*)(Bm + (size_t)n * K + k0 + lc);
            Bs[lc + 0][r] = w.x; Bs[lc + 1][r] = w.y;
            Bs[lc + 2][r] = w.z; Bs[lc + 3][r] = w.w;
        }
        __syncthreads();
#pragma unroll
        for (int k = 0; k < 16; k++) {
            float a[8], b[8];
            *(float4*)(a)     = *(const float4*)(&As[k][ty * 8]);
            *(float4*)(a + 4) = *(const float4*)(&As[k][ty * 8 + 4]);
            *(float4*)(b)     = *(const float4*)(&Bs[k][tx * 8]);
            *(float4*)(b + 4) = *(const float4*)(&Bs[k][tx * 8 + 4]);
#pragma unroll
            for (int i = 0; i < 8; i++)
#pragma unroll
                for (int j = 0; j < 8; j++)
                    acc[i][j] = fmaf(a[i], b[j], acc[i][j]);
        }
        __syncthreads();
    }
#pragma unroll
    for (int i = 0; i < 8; i++) {
        int row = bm + ty * 8 + i;
#pragma unroll
        for (int j4 = 0; j4 < 2; j4++) {
            int col = bn + tx * 8 + j4 * 4;
            if (col + 3 < N) {
                *(float4*)(Cm + (size_t)row * N + col) =
                    make_float4(acc[i][j4 * 4 + 0], acc[i][j4 * 4 + 1],
                                acc[i][j4 * 4 + 2], acc[i][j4 * 4 + 3]);
            } else {
#pragma unroll
                for (int j = 0; j < 4; j++)
                    if (col + j < N)
                        Cm[(size_t)row * N + col + j] = acc[i][j4 * 4 + j];
            }
        }
    }
}

// ---------- AAM per-row reduction (fixed-shift LSE, shift = S) ----------
__global__ void aam_reduce_kernel(const int* __restrict__ label) {
    int r = blockIdx.x;
    const float* row = g_cos + (size_t)r * C_;
    float sexp = 0.f, sout = 0.f;
    for (int j = threadIdx.x; j < C_; j += blockDim.x) {
        float o = K_S * row[j];
        sexp += expf(o - K_S);   // o <= S always (cos<=1), no overflow/underflow issue
        sout += o;
    }
    sexp = block_sum_all(sexp);
    sout = block_sum_all(sout);
    if (threadIdx.x == 0) {
        int y = label[r];
        float cy = row[y];
        float sine = sqrtf(fminf(fmaxf(1.f - cy * cy, 0.f), 1.f));
        float phi = cy * K_COSM - sine * K_SINM;
        phi = (cy - K_TH > 0.f) ? phi : (cy - K_MM);
        float oy  = K_S * phi;
        float ocy = K_S * cy;
        sexp += expf(oy - K_S) - expf(ocy - K_S);  // swap target logit
        sout += oy - ocy;
        float lse = K_S + logf(sexp);
        g_aam_row[r] = (1.f - K_EPS) * (oy - lse) + (K_EPS / C_) * sout - K_EPS * lse;
    }
}

// ---------- ap_m / ap / phi_pm / exp(logit_neg) per row ----------
__global__ void apm_kernel(const int* __restrict__ label) {
    int i = blockIdx.x;
    int li = label[i];
    float ssum = 0.f, cnt = 0.f;
    for (int j = threadIdx.x; j < B_; j += blockDim.x) {
        if (label[j] == li) {
            float sim = g_q[(size_t)i * B_ + j] * g_k[(size_t)i * B_ + j];
            ssum += sim;
            cnt += 1.f;
        }
    }
    ssum = block_sum_all(ssum);
    cnt  = block_sum_all(cnt);
    if (threadIdx.x == 0) {
        float apm = ssum / cnt;  // diagonal always matches -> cnt >= 1
        float ap  = g_q[(size_t)i * B_ + i] * g_k[(size_t)i * B_ + i];
        float cos_ap  = fminf(fmaxf(ap, 0.f), 1.f);
        float sin_ap  = sqrtf(fminf(fmaxf(1.f - cos_ap, 0.f), 1.f));
        float cos_apm = fminf(fmaxf(apm, 0.f), 1.f);
        float sin_apm = sqrtf(fminf(fmaxf(1.f - cos_apm, 0.f), 1.f));
        g_cos_apm[i] = cos_apm;
        g_sin_apm[i] = sin_apm;
        float pc = cos_ap * cos_apm - sin_ap * sin_apm;
        float ps = sqrtf(fminf(fmaxf(1.f - pc, 0.f), 1.f));
        float phi_pm = pc * K_COSM - ps * K_SINM;
        g_expneg[i] = expf(1.f - phi_pm);  // logit_neg <= ~2, direct exp safe
    }
}

// ---------- masked sum of exp(phi_nm) per row (phi_nm <= cos(m) < 1) ----------
__global__ void nm_kernel(const int* __restrict__ label) {
    int i = blockIdx.x;
    int li = label[i];
    float s = 0.f;
    for (int j = threadIdx.x; j < B_; j += blockDim.x) {
        if (label[j] != li) {
            float sim = g_q[(size_t)i * B_ + j] * g_k[(size_t)i * B_ + j];
            float ca = fminf(fmaxf(sim, 0.f), 1.f);
            float sa = sqrtf(fminf(fmaxf(1.f - ca, 0.f), 1.f));
            float ss = sa * g_cos_apm[j] + ca * g_sin_apm[j];  // column-broadcast
            float cc = sqrtf(fminf(fmaxf(1.f - ss, 0.f), 1.f));
            float v = ss * K_COSM - cc * K_SINM;
            s += expf(v);
        }
    }
    s = block_sum_all(s);
    if (threadIdx.x == 0) g_nmp[i] = s;
}

// ---------- final deterministic combine ----------
__global__ void finalize_kernel(float* __restrict__ out) {
    float sa = 0.f, sn = 0.f, sm = 0.f;
    for (int j = threadIdx.x; j < B_; j += blockDim.x) {
        sa += g_aam_row[j];
        sn += g_expneg[j];
        sm += g_nmp[j];
    }
    sa = block_sum_all(sa);
    sn = block_sum_all(sn);
    sm = block_sum_all(sm);
    if (threadIdx.x == 0) {
        float aam_loss = -sa / (float)B_;
        float z = logf(sm) + logf(sn);  // lse_n + lse_neg
        float cc = fmaxf(z, 0.f) + log1pf(expf(-fabsf(z)));  // softplus
        out[0] = aam_loss + cc;
    }
}

// ---------- launcher ----------
extern "C" void kernel_launch(void* const* d_in, const int* in_sizes, int n_in,
                              void* d_out, int out_size) {
    const float* x        = (const float*)d_in[0];
    const int*   label    = (const int*)d_in[1];
    const float* weight   = (const float*)d_in[2];
    const float* weight_m = (const float*)d_in[3];
    const float* weight_n = (const float*)d_in[4];
    float* out = (float*)d_out;

    float *p_xn, *p_wn, *p_wm, *p_wk, *p_cos, *p_q, *p_k;
    cudaGetSymbolAddress((void**)&p_xn,  g_xn);
    cudaGetSymbolAddress((void**)&p_wn,  g_wn);
    cudaGetSymbolAddress((void**)&p_wm,  g_wm);
    cudaGetSymbolAddress((void**)&p_wk,  g_wk);
    cudaGetSymbolAddress((void**)&p_cos, g_cos);
    cudaGetSymbolAddress((void**)&p_q,   g_q);
    cudaGetSymbolAddress((void**)&p_k,   g_k);

    normalize_rows_kernel<<<B_, 128>>>(x, p_xn);
    normalize_rows_kernel<<<C_, 128>>>(weight, p_wn);
    gather_normalize_kernel<<<B_, 128>>>(weight_m, weight_n, label);

    gemm_nt_kernel<<<dim3((C_ + 127) / 128, B_ / 128), 256>>>(p_xn, p_wn, p_cos, C_, D_);
    gemm_nt_kernel<<<dim3(B_ / 128, B_ / 128), 256>>>(p_xn, p_wm, p_q, B_, D_);
    gemm_nt_kernel<<<dim3(B_ / 128, B_ / 128), 256>>>(p_xn, p_wk, p_k, B_, D_);

    aam_reduce_kernel<<<B_, 256>>>(label);
    apm_kernel<<<B_, 256>>>(label);
    nm_kernel<<<B_, 256>>>(label);
    finalize_kernel<<<1, 256>>>(out);
}

// round 2
// speedup vs baseline: 4.2608x; 4.2608x over previous
#include <cuda_runtime.h>
#include <cuda_bf16.h>
#include <math.h>
#include <stdint.h>

#define B_ 2048
#define D_ 512
#define C_ 10000
#define CPAD 10112   // 79 * 128

// ---------- scratch (device globals: alloc-free, capture-safe) ----------
__device__ __nv_bfloat16 g_xh[B_ * D_];             // normalized x (bf16)
__device__ __nv_bfloat16 g_wh[(size_t)CPAD * D_];   // normalized weight (bf16, zero-padded)
__device__ __nv_bfloat16 g_wmh[B_ * D_];            // normalize(weight_m[label]) bf16
__device__ __nv_bfloat16 g_wkh[B_ * D_];            // normalize(weight_n[label]) bf16
__device__ float g_cos[(size_t)B_ * CPAD];          // AAM cosine matrix (padded cols)
__device__ float g_q[(size_t)B_ * B_];
__device__ float g_k[(size_t)B_ * B_];
__device__ float g_aam_row[B_];
__device__ float g_expneg[B_];
__device__ float g_nmp[B_];
__device__ float g_cos_apm[B_];
__device__ float g_sin_apm[B_];

// ---------- constants ----------
constexpr float K_S    = 30.0f;
constexpr float K_COSM = 0.9800665778412416f;   // cos(0.2)
constexpr float K_SINM = 0.19866933079506122f;  // sin(0.2)
constexpr float K_TH   = -0.9800665778412416f;  // cos(pi - 0.2)
constexpr float K_MM   = 0.039733866159012244f; // sin(pi-0.2)*0.2
constexpr float K_EPS  = 0.1f;

// ---------- MUFU-free exp (FFMA pipe; |x| < 87) ----------
__device__ __forceinline__ float fexp(float x) {
    float t = x * 1.4426950408889634f;     // x * log2(e)
    int   i = __float2int_rn(t);
    float f = t - (float)i;                // f in [-0.5, 0.5]
    float p = 1.3333558146e-3f;
    p = fmaf(p, f, 9.6181291076e-3f);
    p = fmaf(p, f, 5.5504108665e-2f);
    p = fmaf(p, f, 2.4022650696e-1f);
    p = fmaf(p, f, 6.9314718056e-1f);
    p = fmaf(p, f, 1.0f);                  // 2^f
    float s = __int_as_float((i + 127) << 23);
    return p * s;
}

// ---------- MUFU-free sqrt for y in [0,1] (bit-hack rsqrt + 3 Newton) ----------
__device__ __forceinline__ float fsqrt_fast(float y) {
    y = fmaxf(y, 1e-30f);
    float g = __uint_as_float(0x5f3759dfu - (__float_as_uint(y) >> 1));
    g = g * fmaf(-0.5f * y * g, g, 1.5f);
    g = g * fmaf(-0.5f * y * g, g, 1.5f);
    g = g * fmaf(-0.5f * y * g, g, 1.5f);
    return y * g;
}

// ---------- block-wide sum (result broadcast to all threads) ----------
__device__ __forceinline__ float block_sum_all(float v) {
    __shared__ float sh[33];
    int lane = threadIdx.x & 31, wid = threadIdx.x >> 5;
#pragma unroll
    for (int o = 16; o; o >>= 1) v += __shfl_down_sync(0xffffffffu, v, o);
    __syncthreads();
    if (lane == 0) sh[wid] = v;
    __syncthreads();
    if (threadIdx.x == 0) {
        float s = 0.f;
        int nw = (blockDim.x + 31) >> 5;
        for (int w = 0; w < nw; w++) s += sh[w];
        sh[32] = s;
    }
    __syncthreads();
    return sh[32];
}

// ---------- row L2-normalize -> bf16 (rowlen 512, 128 threads/row) ----------
__global__ void normalize_bf16_kernel(const float* __restrict__ src,
                                      __nv_bfloat16* __restrict__ dst,
                                      int nrows) {
    int r = blockIdx.x;
    int t = threadIdx.x;
    __nv_bfloat162* o2 = (__nv_bfloat162*)(dst + (size_t)r * D_ + t * 4);
    if (r >= nrows) {  // zero pad rows (uniform per block)
        __nv_bfloat162 z = __float2bfloat162_rn(0.f);
        o2[0] = z; o2[1] = z;
        return;
    }
    const float4 v = *(const float4*)(src + (size_t)r * D_ + t * 4);
    float ss = v.x * v.x + v.y * v.y + v.z * v.z + v.w * v.w;
    float tot = block_sum_all(ss);
    float inv = 1.0f / fmaxf(sqrtf(tot), 1e-12f);
    o2[0] = __floats2bfloat162_rn(v.x * inv, v.y * inv);
    o2[1] = __floats2bfloat162_rn(v.z * inv, v.w * inv);
}

// ---------- gather + normalize weight_m[label], weight_n[label] -> bf16 ----------
__global__ void gather_normalize_kernel(const float* __restrict__ wm,
                                        const float* __restrict__ wk,
                                        const int* __restrict__ label) {
    int i = blockIdx.x;
    int t = threadIdx.x;
    int c = label[i];
    {
        const float4 v = *(const float4*)(wm + (size_t)c * D_ + t * 4);
        float tot = block_sum_all(v.x * v.x + v.y * v.y + v.z * v.z + v.w * v.w);
        float inv = 1.0f / fmaxf(sqrtf(tot), 1e-12f);
        __nv_bfloat162* o2 = (__nv_bfloat162*)(g_wmh + (size_t)i * D_ + t * 4);
        o2[0] = __floats2bfloat162_rn(v.x * inv, v.y * inv);
        o2[1] = __floats2bfloat162_rn(v.z * inv, v.w * inv);
    }
    {
        const float4 v = *(const float4*)(wk + (size_t)c * D_ + t * 4);
        float tot = block_sum_all(v.x * v.x + v.y * v.y + v.z * v.z + v.w * v.w);
        float inv = 1.0f / fmaxf(sqrtf(tot), 1e-12f);
        __nv_bfloat162* o2 = (__nv_bfloat162*)(g_wkh + (size_t)i * D_ + t * 4);
        o2[0] = __floats2bfloat162_rn(v.x * inv, v.y * inv);
        o2[1] = __floats2bfloat162_rn(v.z * inv, v.w * inv);
    }
}

// ================= bf16 tensor-core GEMM: C[m,n] = sum_k A[m,k]*B[n,k] =================
// A:[M,K] bf16 row-major, B:[N,K] bf16 row-major, C fp32 [M,N].
// M,N multiples of 128, K multiple of 32. 128x128x32 tile, 256 thr, 8 warps (4m x 2n).

__device__ __forceinline__ void ldsm4(uint32_t& r0, uint32_t& r1, uint32_t& r2, uint32_t& r3,
                                      uint32_t addr) {
    asm volatile("ldmatrix.sync.aligned.m8n8.x4.shared.b16 {%0,%1,%2,%3},[%4];\n"
                 : "=r"(r0), "=r"(r1), "=r"(r2), "=r"(r3) : "r"(addr));
}
__device__ __forceinline__ void mma16816(float* c, const uint32_t* a, uint32_t b0, uint32_t b1) {
    asm volatile(
        "mma.sync.aligned.m16n8k16.row.col.f32.bf16.bf16.f32 "
        "{%0,%1,%2,%3},{%4,%5,%6,%7},{%8,%9},{%0,%1,%2,%3};\n"
        : "+f"(c[0]), "+f"(c[1]), "+f"(c[2]), "+f"(c[3])
        : "r"(a[0]), "r"(a[1]), "r"(a[2]), "r"(a[3]), "r"(b0), "r"(b1));
}
__device__ __forceinline__ void cpasync16(uint32_t s, const void* g) {
    asm volatile("cp.async.cg.shared.global [%0],[%1],16;\n" :: "r"(s), "l"(g));
}

#define ROWB 80          // bytes per smem row (40 bf16): conflict-free ldmatrix stride
#define STAGEB (128 * ROWB)

__global__ void __launch_bounds__(256, 2)
gemm_bf16_nt(const __nv_bfloat16* __restrict__ A, const __nv_bfloat16* __restrict__ Bm,
             float* __restrict__ Cm, int N, int K) {
    __shared__ __align__(16) __nv_bfloat16 As[2][128 * 40];
    __shared__ __align__(16) __nv_bfloat16 Bs[2][128 * 40];

    int tid = threadIdx.x, lane = tid & 31, warp = tid >> 5;
    int wm = warp >> 1, wn = warp & 1;
    int bm = blockIdx.y * 128, bn = blockIdx.x * 128;

    uint32_t sA0 = (uint32_t)__cvta_generic_to_shared(&As[0][0]);
    uint32_t sB0 = (uint32_t)__cvta_generic_to_shared(&Bs[0][0]);

    float acc[2][8][4];
#pragma unroll
    for (int mi = 0; mi < 2; mi++)
#pragma unroll
        for (int ni = 0; ni < 8; ni++)
#pragma unroll
            for (int e = 0; e < 4; e++) acc[mi][ni][e] = 0.f;

    // ldmatrix lane offsets (bytes within a stage)
    int aRow = wm * 32 + (lane & 7) + ((lane >> 3) & 1) * 8;
    int aCol = ((lane >> 4) & 1) * 16;
    int bRow = wn * 64 + (lane & 7) + ((lane >> 4) & 1) * 8;
    int bCol = ((lane >> 3) & 1) * 16;
    uint32_t aOff[2], bOff[4];
#pragma unroll
    for (int mi = 0; mi < 2; mi++) aOff[mi] = sA0 + (uint32_t)((aRow + mi * 16) * ROWB + aCol);
#pragma unroll
    for (int nn = 0; nn < 4; nn++) bOff[nn] = sB0 + (uint32_t)((bRow + nn * 16) * ROWB + bCol);

    // loader: each thread copies 2 x 16B for A and for B per stage
    int c0r = tid >> 2, c0k = tid & 3;            // chunk tid
    int c1r = (tid + 256) >> 2, c1k = tid & 3;    // chunk tid+256

    const int NIT = K / 32;  // 16
    // prologue: stages 0 and 1
#pragma unroll
    for (int pre = 0; pre < 2; pre++) {
        int k0 = pre * 32;
        uint32_t sa = sA0 + pre * STAGEB, sb = sB0 + pre * STAGEB;
        cpasync16(sa + c0r * ROWB + c0k * 16, A + (size_t)(bm + c0r) * K + k0 + c0k * 8);
        cpasync16(sa + c1r * ROWB + c1k * 16, A + (size_t)(bm + c1r) * K + k0 + c1k * 8);
        cpasync16(sb + c0r * ROWB + c0k * 16, Bm + (size_t)(bn + c0r) * K + k0 + c0k * 8);
        cpasync16(sb + c1r * ROWB + c1k * 16, Bm + (size_t)(bn + c1r) * K + k0 + c1k * 8);
        asm volatile("cp.async.commit_group;\n");
    }

    for (int it = 0; it < NIT; it++) {
        if (it < NIT - 2) asm volatile("cp.async.wait_group 1;\n");
        else              asm volatile("cp.async.wait_group 0;\n");
        __syncthreads();

        uint32_t soff = (uint32_t)((it & 1) * STAGEB);
#pragma unroll
        for (int ks = 0; ks < 2; ks++) {
            uint32_t a[2][4];
            ldsm4(a[0][0], a[0][1], a[0][2], a[0][3], aOff[0] + soff + ks * 32);
            ldsm4(a[1][0], a[1][1], a[1][2], a[1][3], aOff[1] + soff + ks * 32);
            uint32_t b[8][2];
#pragma unroll
            for (int nn = 0; nn < 4; nn++) {
                uint32_t r0, r1, r2, r3;
                ldsm4(r0, r1, r2, r3, bOff[nn] + soff + ks * 32);
                b[2 * nn][0] = r0; b[2 * nn][1] = r1;
                b[2 * nn + 1][0] = r2; b[2 * nn + 1][1] = r3;
            }
#pragma unroll
            for (int mi = 0; mi < 2; mi++)
#pragma unroll
                for (int ni = 0; ni < 8; ni++)
                    mma16816(acc[mi][ni], a[mi], b[ni][0], b[ni][1]);
        }
        __syncthreads();
        if (it + 2 < NIT) {
            int k0 = (it + 2) * 32;
            uint32_t sa = sA0 + soff, sb = sB0 + soff;  // reuse freed stage (it&1)
            cpasync16(sa + c0r * ROWB + c0k * 16, A + (size_t)(bm + c0r) * K + k0 + c0k * 8);
            cpasync16(sa + c1r * ROWB + c1k * 16, A + (size_t)(bm + c1r) * K + k0 + c1k * 8);
            cpasync16(sb + c0r * ROWB + c0k * 16, Bm + (size_t)(bn + c0r) * K + k0 + c0k * 8);
            cpasync16(sb + c1r * ROWB + c1k * 16, Bm + (size_t)(bn + c1r) * K + k0 + c1k * 8);
            asm volatile("cp.async.commit_group;\n");
        }
    }

    // epilogue: fp32 stores (all blocks full thanks to padding)
#pragma unroll
    for (int mi = 0; mi < 2; mi++) {
        int r0 = bm + wm * 32 + mi * 16 + (lane >> 2);
#pragma unroll
        for (int ni = 0; ni < 8; ni++) {
            int c0 = bn + wn * 64 + ni * 8 + (lane & 3) * 2;
            *(float2*)(Cm + (size_t)r0 * N + c0) = make_float2(acc[mi][ni][0], acc[mi][ni][1]);
            *(float2*)(Cm + (size_t)(r0 + 8) * N + c0) = make_float2(acc[mi][ni][2], acc[mi][ni][3]);
        }
    }
}

// ---------- AAM per-row reduction (fixed-shift LSE, shift = S) ----------
__global__ void aam_reduce_kernel(const int* __restrict__ label) {
    int r = blockIdx.x;
    const float4* row = (const float4*)(g_cos + (size_t)r * CPAD);
    float sexp = 0.f, sc = 0.f;
    for (int j = threadIdx.x; j < C_ / 4; j += blockDim.x) {
        float4 v = row[j];
        sc += v.x + v.y + v.z + v.w;
        sexp += fexp(K_S * (v.x - 1.f));
        sexp += fexp(K_S * (v.y - 1.f));
        sexp += fexp(K_S * (v.z - 1.f));
        sexp += fexp(K_S * (v.w - 1.f));
    }
    sexp = block_sum_all(sexp);
    sc   = block_sum_all(sc);
    if (threadIdx.x == 0) {
        int y = label[r];
        float cy = g_cos[(size_t)r * CPAD + y];
        float sine = sqrtf(fminf(fmaxf(1.f - cy * cy, 0.f), 1.f));
        float phi = cy * K_COSM - sine * K_SINM;
        phi = (cy - K_TH > 0.f) ? phi : (cy - K_MM);
        float oy  = K_S * phi;
        float ocy = K_S * cy;
        float sout = K_S * sc + (oy - ocy);
        sexp += fexp(oy - K_S) - fexp(ocy - K_S);  // swap target logit
        float lse = K_S + logf(sexp);
        g_aam_row[r] = (1.f - K_EPS) * (oy - lse) + (K_EPS / C_) * sout - K_EPS * lse;
    }
}

// ---------- ap_m / ap / phi_pm / exp(logit_neg) per row ----------
__global__ void apm_kernel(const int* __restrict__ label) {
    int i = blockIdx.x;
    int li = label[i];
    float ssum = 0.f, cnt = 0.f;
    for (int j = threadIdx.x; j < B_; j += blockDim.x) {
        if (label[j] == li) {
            float sim = g_q[(size_t)i * B_ + j] * g_k[(size_t)i * B_ + j];
            ssum += sim;
            cnt += 1.f;
        }
    }
    ssum = block_sum_all(ssum);
    cnt  = block_sum_all(cnt);
    if (threadIdx.x == 0) {
        float apm = ssum / cnt;
        float ap  = g_q[(size_t)i * B_ + i] * g_k[(size_t)i * B_ + i];
        float cos_ap  = fminf(fmaxf(ap, 0.f), 1.f);
        float sin_ap  = fsqrt_fast(fminf(fmaxf(1.f - cos_ap, 0.f), 1.f));
        float cos_apm = fminf(fmaxf(apm, 0.f), 1.f);
        float sin_apm = fsqrt_fast(fminf(fmaxf(1.f - cos_apm, 0.f), 1.f));
        g_cos_apm[i] = cos_apm;
        g_sin_apm[i] = sin_apm;
        float pc = cos_ap * cos_apm - sin_ap * sin_apm;
        float ps = fsqrt_fast(fminf(fmaxf(1.f - pc, 0.f), 1.f));
        float phi_pm = pc * K_COSM - ps * K_SINM;
        g_expneg[i] = fexp(1.f - phi_pm);
    }
}

// ---------- masked sum of exp(phi_nm) per row ----------
__global__ void nm_kernel(const int* __restrict__ label) {
    int i = blockIdx.x;
    int li = label[i];
    float s = 0.f;
    for (int j = threadIdx.x; j < B_; j += blockDim.x) {
        if (label[j] != li) {
            float sim = g_q[(size_t)i * B_ + j] * g_k[(size_t)i * B_ + j];
            float ca = fminf(fmaxf(sim, 0.f), 1.f);
            float sa = fsqrt_fast(fminf(fmaxf(1.f - ca, 0.f), 1.f));
            float ss = sa * g_cos_apm[j] + ca * g_sin_apm[j];
            float cc = fsqrt_fast(fminf(fmaxf(1.f - ss, 0.f), 1.f));
            float v = ss * K_COSM - cc * K_SINM;
            s += fexp(v);
        }
    }
    s = block_sum_all(s);
    if (threadIdx.x == 0) g_nmp[i] = s;
}

// ---------- final deterministic combine ----------
__global__ void finalize_kernel(float* __restrict__ out) {
    float sa = 0.f, sn = 0.f, sm = 0.f;
    for (int j = threadIdx.x; j < B_; j += blockDim.x) {
        sa += g_aam_row[j];
        sn += g_expneg[j];
        sm += g_nmp[j];
    }
    sa = block_sum_all(sa);
    sn = block_sum_all(sn);
    sm = block_sum_all(sm);
    if (threadIdx.x == 0) {
        float aam_loss = -sa / (float)B_;
        float z = logf(sm) + logf(sn);                       // lse_n + lse_neg
        float cc = fmaxf(z, 0.f) + log1pf(expf(-fabsf(z)));  // softplus
        out[0] = aam_loss + cc;
    }
}

// ---------- launcher ----------
extern "C" void kernel_launch(void* const* d_in, const int* in_sizes, int n_in,
                              void* d_out, int out_size) {
    const float* x        = (const float*)d_in[0];
    const int*   label    = (const int*)d_in[1];
    const float* weight   = (const float*)d_in[2];
    const float* weight_m = (const float*)d_in[3];
    const float* weight_n = (const float*)d_in[4];
    float* out = (float*)d_out;

    __nv_bfloat16 *p_xh, *p_wh, *p_wmh, *p_wkh;
    float *p_cos, *p_q, *p_k;
    cudaGetSymbolAddress((void**)&p_xh,  g_xh);
    cudaGetSymbolAddress((void**)&p_wh,  g_wh);
    cudaGetSymbolAddress((void**)&p_wmh, g_wmh);
    cudaGetSymbolAddress((void**)&p_wkh, g_wkh);
    cudaGetSymbolAddress((void**)&p_cos, g_cos);
    cudaGetSymbolAddress((void**)&p_q,   g_q);
    cudaGetSymbolAddress((void**)&p_k,   g_k);

    normalize_bf16_kernel<<<B_, 128>>>(x, p_xh, B_);
    normalize_bf16_kernel<<<CPAD, 128>>>(weight, p_wh, C_);  // zero-pads rows C_..CPAD
    gather_normalize_kernel<<<B_, 128>>>(weight_m, weight_n, label);

    gemm_bf16_nt<<<dim3(CPAD / 128, B_ / 128), 256>>>(p_xh, p_wh, p_cos, CPAD, D_);
    gemm_bf16_nt<<<dim3(B_ / 128, B_ / 128), 256>>>(p_xh, p_wmh, p_q, B_, D_);
    gemm_bf16_nt<<<dim3(B_ / 128, B_ / 128), 256>>>(p_xh, p_wkh, p_k, B_, D_);

    aam_reduce_kernel<<<B_, 256>>>(label);
    apm_kernel<<<B_, 256>>>(label);
    nm_kernel<<<B_, 256>>>(label);
    finalize_kernel<<<1, 256>>>(out);
}

// round 4
// speedup vs baseline: 4.7780x; 1.1214x over previous
#include <cuda_runtime.h>
#include <cuda_bf16.h>
#include <math.h>
#include <stdint.h>

#define B_ 2048
#define D_ 512
#define C_ 10000
#define CPAD 10112          // 79 * 128
#define NTC 79              // col tiles of 128
#define NPART (NTC * 2)     // 158 partials per row (2 warp col-halves per tile)

// ---------- scratch (device globals: alloc-free, capture-safe) ----------
__device__ __nv_bfloat16 g_xh[B_ * D_];
__device__ __nv_bfloat16 g_wh[(size_t)CPAD * D_];
__device__ __nv_bfloat16 g_wmh[B_ * D_];
__device__ __nv_bfloat16 g_wkh[B_ * D_];
__device__ float g_q[(size_t)B_ * B_];
__device__ float g_k[(size_t)B_ * B_];
__device__ float g_pexp[(size_t)B_ * NPART];
__device__ float g_psum[(size_t)B_ * NPART];
__device__ float g_cy[B_];
__device__ float g_aam_row[B_];
__device__ float g_expneg[B_];
__device__ float g_nmp[B_];
__device__ float g_cos_apm[B_];
__device__ float g_sin_apm[B_];

// ---------- constants ----------
constexpr float K_S    = 30.0f;
constexpr float K_COSM = 0.9800665778412416f;
constexpr float K_SINM = 0.19866933079506122f;
constexpr float K_TH   = -0.9800665778412416f;
constexpr float K_MM   = 0.039733866159012244f;
constexpr float K_EPS  = 0.1f;
constexpr float K_L2E  = 1.4426950408889634f;

// ---------- fast math (MUFU) ----------
__device__ __forceinline__ float exp_approx(float x) {
    float r;
    asm("ex2.approx.f32 %0, %1;" : "=f"(r) : "f"(x * K_L2E));
    return r;
}
__device__ __forceinline__ float sqrt_approx(float x) {
    float r;
    asm("sqrt.approx.f32 %0, %1;" : "=f"(r) : "f"(x));
    return r;
}

// ---------- block-wide sum ----------
__device__ __forceinline__ float block_sum_all(float v) {
    __shared__ float sh[33];
    int lane = threadIdx.x & 31, wid = threadIdx.x >> 5;
#pragma unroll
    for (int o = 16; o; o >>= 1) v += __shfl_down_sync(0xffffffffu, v, o);
    __syncthreads();
    if (lane == 0) sh[wid] = v;
    __syncthreads();
    if (threadIdx.x == 0) {
        float s = 0.f;
        int nw = (blockDim.x + 31) >> 5;
        for (int w = 0; w < nw; w++) s += sh[w];
        sh[32] = s;
    }
    __syncthreads();
    return sh[32];
}

// ---------- normalize -> bf16 ----------
__global__ void normalize_bf16_kernel(const float* __restrict__ src,
                                      __nv_bfloat16* __restrict__ dst, int nrows) {
    int r = blockIdx.x, t = threadIdx.x;
    __nv_bfloat162* o2 = (__nv_bfloat162*)(dst + (size_t)r * D_ + t * 4);
    if (r >= nrows) {
        __nv_bfloat162 z = __float2bfloat162_rn(0.f);
        o2[0] = z; o2[1] = z;
        return;
    }
    const float4 v = *(const float4*)(src + (size_t)r * D_ + t * 4);
    float tot = block_sum_all(v.x * v.x + v.y * v.y + v.z * v.z + v.w * v.w);
    float inv = 1.0f / fmaxf(sqrtf(tot), 1e-12f);
    o2[0] = __floats2bfloat162_rn(v.x * inv, v.y * inv);
    o2[1] = __floats2bfloat162_rn(v.z * inv, v.w * inv);
}

__global__ void gather_normalize_kernel(const float* __restrict__ wm,
                                        const float* __restrict__ wk,
                                        const int* __restrict__ label) {
    int i = blockIdx.x, t = threadIdx.x;
    int c = label[i];
    {
        const float4 v = *(const float4*)(wm + (size_t)c * D_ + t * 4);
        float tot = block_sum_all(v.x * v.x + v.y * v.y + v.z * v.z + v.w * v.w);
        float inv = 1.0f / fmaxf(sqrtf(tot), 1e-12f);
        __nv_bfloat162* o2 = (__nv_bfloat162*)(g_wmh + (size_t)i * D_ + t * 4);
        o2[0] = __floats2bfloat162_rn(v.x * inv, v.y * inv);
        o2[1] = __floats2bfloat162_rn(v.z * inv, v.w * inv);
    }
    {
        const float4 v = *(const float4*)(wk + (size_t)c * D_ + t * 4);
        float tot = block_sum_all(v.x * v.x + v.y * v.y + v.z * v.z + v.w * v.w);
        float inv = 1.0f / fmaxf(sqrtf(tot), 1e-12f);
        __nv_bfloat162* o2 = (__nv_bfloat162*)(g_wkh + (size_t)i * D_ + t * 4);
        o2[0] = __floats2bfloat162_rn(v.x * inv, v.y * inv);
        o2[1] = __floats2bfloat162_rn(v.z * inv, v.w * inv);
    }
}

// ============== mma.sync bf16 building blocks ==============
__device__ __forceinline__ void ldsm4(uint32_t& r0, uint32_t& r1, uint32_t& r2, uint32_t& r3,
                                      uint32_t addr) {
    asm volatile("ldmatrix.sync.aligned.m8n8.x4.shared.b16 {%0,%1,%2,%3},[%4];\n"
                 : "=r"(r0), "=r"(r1), "=r"(r2), "=r"(r3) : "r"(addr));
}
__device__ __forceinline__ void mma16816(float* c, const uint32_t* a, uint32_t b0, uint32_t b1) {
    asm volatile("mma.sync.aligned.m16n8k16.row.col.f32.bf16.bf16.f32 "
                 "{%0,%1,%2,%3},{%4,%5,%6,%7},{%8,%9},{%0,%1,%2,%3};\n"
                 : "+f"(c[0]), "+f"(c[1]), "+f"(c[2]), "+f"(c[3])
                 : "r"(a[0]), "r"(a[1]), "r"(a[2]), "r"(a[3]), "r"(b0), "r"(b1));
}
__device__ __forceinline__ void cpasync16(uint32_t s, const void* g) {
    asm volatile("cp.async.cg.shared.global [%0],[%1],16;\n" :: "r"(s), "l"(g));
}

#define ROWB 80               // bytes per smem row (40 bf16) - conflict-free ldmatrix
#define HALFB (128 * ROWB)    // one matrix (128 rows) in a stage: 10240 B
#define STAGEB (2 * HALFB)    // A + B per stage: 20480 B
#define NSTAGE 3
#define GEMM_SMEM (NSTAGE * STAGEB)   // 61440 B

// GEMM skeleton macro-body shared by both kernels via helpers:
struct TileCtx {
    uint32_t sA0, sB0;        // stage-0 bases
    uint32_t aOff[2], bOff[4];
    int c0r, c0k, c1r, c1k;
    int wm, wn, lane;
};

__device__ __forceinline__ void tile_init(TileCtx& T, uint32_t sbase, int tid) {
    int lane = tid & 31, warp = tid >> 5;
    T.lane = lane;
    T.wm = warp >> 1; T.wn = warp & 1;
    T.sA0 = sbase;
    T.sB0 = sbase + HALFB;
    int aRow = T.wm * 32 + (lane & 7) + ((lane >> 3) & 1) * 8;
    int aCol = ((lane >> 4) & 1) * 16;
    int bRow = T.wn * 64 + (lane & 7) + ((lane >> 4) & 1) * 8;
    int bCol = ((lane >> 3) & 1) * 16;
#pragma unroll
    for (int mi = 0; mi < 2; mi++) T.aOff[mi] = T.sA0 + (uint32_t)((aRow + mi * 16) * ROWB + aCol);
#pragma unroll
    for (int nn = 0; nn < 4; nn++) T.bOff[nn] = T.sB0 + (uint32_t)((bRow + nn * 16) * ROWB + bCol);
    T.c0r = tid >> 2;          T.c0k = tid & 3;
    T.c1r = (tid + 256) >> 2;  T.c1k = tid & 3;
}

__device__ __forceinline__ void tile_load(const TileCtx& T, int stage,
                                          const __nv_bfloat16* A, const __nv_bfloat16* Bm,
                                          int bm, int bn, int k0, int K) {
    uint32_t sa = T.sA0 + stage * STAGEB, sb = T.sB0 + stage * STAGEB;
    cpasync16(sa + T.c0r * ROWB + T.c0k * 16, A + (size_t)(bm + T.c0r) * K + k0 + T.c0k * 8);
    cpasync16(sa + T.c1r * ROWB + T.c1k * 16, A + (size_t)(bm + T.c1r) * K + k0 + T.c1k * 8);
    cpasync16(sb + T.c0r * ROWB + T.c0k * 16, Bm + (size_t)(bn + T.c0r) * K + k0 + T.c0k * 8);
    cpasync16(sb + T.c1r * ROWB + T.c1k * 16, Bm + (size_t)(bn + T.c1r) * K + k0 + T.c1k * 8);
    asm volatile("cp.async.commit_group;\n");
}

__device__ __forceinline__ void tile_compute(const TileCtx& T, int stage, float acc[2][8][4]) {
    uint32_t soff = (uint32_t)(stage * STAGEB);
#pragma unroll
    for (int ks = 0; ks < 2; ks++) {
        uint32_t a[2][4];
        ldsm4(a[0][0], a[0][1], a[0][2], a[0][3], T.aOff[0] + soff + ks * 32);
        ldsm4(a[1][0], a[1][1], a[1][2], a[1][3], T.aOff[1] + soff + ks * 32);
        uint32_t b[8][2];
#pragma unroll
        for (int nn = 0; nn < 4; nn++) {
            uint32_t r0, r1, r2, r3;
            ldsm4(r0, r1, r2, r3, T.bOff[nn] + soff + ks * 32);
            b[2 * nn][0] = r0; b[2 * nn][1] = r1;
            b[2 * nn + 1][0] = r2; b[2 * nn + 1][1] = r3;
        }
#pragma unroll
        for (int mi = 0; mi < 2; mi++)
#pragma unroll
            for (int ni = 0; ni < 8; ni++)
                mma16816(acc[mi][ni], a[mi], b[ni][0], b[ni][1]);
    }
}

// mainloop: 3-stage, single __syncthreads per iteration
#define GEMM_MAINLOOP(T, A, Bm, bm, bn, K, acc) do {                      \
    const int NIT = (K) / 32;                                             \
    tile_load(T, 0, A, Bm, bm, bn, 0, K);                                 \
    tile_load(T, 1, A, Bm, bm, bn, 32, K);                                \
    for (int it = 0; it < NIT; it++) {                                    \
        if (it < NIT - 1) asm volatile("cp.async.wait_group 1;\n");       \
        else              asm volatile("cp.async.wait_group 0;\n");       \
        __syncthreads();                                                  \
        int st = it % NSTAGE;                                             \
        tile_compute(T, st, acc);                                         \
        if (it + 2 < NIT)                                                 \
            tile_load(T, (it + 2) % NSTAGE, A, Bm, bm, bn, (it + 2) * 32, K); \
    }                                                                     \
} while (0)

// ============== big GEMM with fused AAM epilogue (cosine never stored) ==============
__global__ void __launch_bounds__(256)
gemm_fused_aam(const __nv_bfloat16* __restrict__ A, const __nv_bfloat16* __restrict__ Bw,
               const int* __restrict__ label) {
    extern __shared__ __align__(16) char smem[];
    int tid = threadIdx.x;
    int bm = blockIdx.y * 128, bn = blockIdx.x * 128;
    TileCtx T;
    tile_init(T, (uint32_t)__cvta_generic_to_shared(smem), tid);

    float acc[2][8][4];
#pragma unroll
    for (int mi = 0; mi < 2; mi++)
#pragma unroll
        for (int ni = 0; ni < 8; ni++)
#pragma unroll
            for (int e = 0; e < 4; e++) acc[mi][ni][e] = 0.f;

    GEMM_MAINLOOP(T, A, Bw, bm, bn, D_, acc);

    // fused AAM epilogue: per-thread rows, quad reduce, write partials
    int lane = T.lane;
    int colbase = bn + T.wn * 64 + (lane & 3) * 2;
#pragma unroll
    for (int mi = 0; mi < 2; mi++) {
#pragma unroll
        for (int h = 0; h < 2; h++) {
            int row = bm + T.wm * 32 + mi * 16 + (lane >> 2) + h * 8;
            int lab = label[row];
            float se = 0.f, sc = 0.f, cy = 0.f;
#pragma unroll
            for (int ni = 0; ni < 8; ni++) {
                int col = colbase + ni * 8;
                float v0 = acc[mi][ni][h * 2 + 0];
                float v1 = acc[mi][ni][h * 2 + 1];
                if (col < C_) {
                    sc += v0;
                    se += exp_approx(K_S * (v0 - 1.f));
                    if (col == lab) cy = v0;
                }
                if (col + 1 < C_) {
                    sc += v1;
                    se += exp_approx(K_S * (v1 - 1.f));
                    if (col + 1 == lab) cy = v1;
                }
            }
            se += __shfl_xor_sync(0xffffffffu, se, 1);
            se += __shfl_xor_sync(0xffffffffu, se, 2);
            sc += __shfl_xor_sync(0xffffffffu, sc, 1);
            sc += __shfl_xor_sync(0xffffffffu, sc, 2);
            cy += __shfl_xor_sync(0xffffffffu, cy, 1);
            cy += __shfl_xor_sync(0xffffffffu, cy, 2);
            if ((lane & 3) == 0) {
                int part = blockIdx.x * 2 + T.wn;
                g_pexp[(size_t)row * NPART + part] = se;
                g_psum[(size_t)row * NPART + part] = sc;
                int cb = bn + T.wn * 64;
                if (lab >= cb && lab < cb + 64) g_cy[row] = cy;
            }
        }
    }
}

// ============== plain GEMM (q, k): same pipeline, stores C ==============
__global__ void __launch_bounds__(256)
gemm_bf16_nt(const __nv_bfloat16* __restrict__ A, const __nv_bfloat16* __restrict__ Bm,
             float* __restrict__ Cm, int N, int K) {
    extern __shared__ __align__(16) char smem[];
    int tid = threadIdx.x;
    int bm = blockIdx.y * 128, bn = blockIdx.x * 128;
    TileCtx T;
    tile_init(T, (uint32_t)__cvta_generic_to_shared(smem), tid);

    float acc[2][8][4];
#pragma unroll
    for (int mi = 0; mi < 2; mi++)
#pragma unroll
        for (int ni = 0; ni < 8; ni++)
#pragma unroll
            for (int e = 0; e < 4; e++) acc[mi][ni][e] = 0.f;

    GEMM_MAINLOOP(T, A, Bm, bm, bn, K, acc);

    int lane = T.lane;
#pragma unroll
    for (int mi = 0; mi < 2; mi++) {
        int r0 = bm + T.wm * 32 + mi * 16 + (lane >> 2);
#pragma unroll
        for (int ni = 0; ni < 8; ni++) {
            int c0 = bn + T.wn * 64 + ni * 8 + (lane & 3) * 2;
            *(float2*)(Cm + (size_t)r0 * N + c0) = make_float2(acc[mi][ni][0], acc[mi][ni][1]);
            *(float2*)(Cm + (size_t)(r0 + 8) * N + c0) = make_float2(acc[mi][ni][2], acc[mi][ni][3]);
        }
    }
}

// ---------- AAM per-row finalize (warp per row) ----------
__global__ void aam_finalize(const int* __restrict__ label) {
    int row = blockIdx.x * 8 + (threadIdx.x >> 5);
    int lane = threadIdx.x & 31;
    float se = 0.f, sc = 0.f;
    for (int j = lane; j < NPART; j += 32) {
        se += g_pexp[(size_t)row * NPART + j];
        sc += g_psum[(size_t)row * NPART + j];
    }
#pragma unroll
    for (int o = 16; o; o >>= 1) {
        se += __shfl_down_sync(0xffffffffu, se, o);
        sc += __shfl_down_sync(0xffffffffu, sc, o);
    }
    if (lane == 0) {
        float cyv = g_cy[row];
        float sine = sqrtf(fminf(fmaxf(1.f - cyv * cyv, 0.f), 1.f));
        float phi = cyv * K_COSM - sine * K_SINM;
        phi = (cyv - K_TH > 0.f) ? phi : (cyv - K_MM);
        float oy = K_S * phi, ocy = K_S * cyv;
        float sout = K_S * sc + (oy - ocy);
        se += expf(oy - K_S) - expf(ocy - K_S);  // swap target logit
        float lse = K_S + logf(se);
        g_aam_row[row] = (1.f - K_EPS) * (oy - lse) + (K_EPS / C_) * sout - K_EPS * lse;
    }
}

// ---------- ap_m / ap / exp(logit_neg): label-gated loads ----------
__global__ void apm_kernel(const int* __restrict__ label) {
    __shared__ int slab[B_];
    for (int j = threadIdx.x; j < B_; j += blockDim.x) slab[j] = label[j];
    __syncthreads();
    int i = blockIdx.x;
    int li = slab[i];
    float ssum = 0.f, cnt = 0.f;
    for (int j = threadIdx.x; j < B_; j += blockDim.x) {
        if (slab[j] == li) {
            ssum += g_q[(size_t)i * B_ + j] * g_k[(size_t)i * B_ + j];
            cnt += 1.f;
        }
    }
    ssum = block_sum_all(ssum);
    cnt  = block_sum_all(cnt);
    if (threadIdx.x == 0) {
        float apm = ssum / cnt;
        float ap  = g_q[(size_t)i * B_ + i] * g_k[(size_t)i * B_ + i];
        float cos_ap  = fminf(fmaxf(ap, 0.f), 1.f);
        float sin_ap  = sqrt_approx(fminf(fmaxf(1.f - cos_ap, 0.f), 1.f));
        float cos_apm = fminf(fmaxf(apm, 0.f), 1.f);
        float sin_apm = sqrt_approx(fminf(fmaxf(1.f - cos_apm, 0.f), 1.f));
        g_cos_apm[i] = cos_apm;
        g_sin_apm[i] = sin_apm;
        float pc = cos_ap * cos_apm - sin_ap * sin_apm;
        float ps = sqrt_approx(fminf(fmaxf(1.f - pc, 0.f), 1.f));
        float phi_pm = pc * K_COSM - ps * K_SINM;
        g_expneg[i] = exp_approx(1.f - phi_pm);
    }
}

// ---------- masked sum of exp(phi_nm) per row ----------
__global__ void nm_kernel(const int* __restrict__ label) {
    __shared__ int slab[B_];
    for (int j = threadIdx.x; j < B_; j += blockDim.x) slab[j] = label[j];
    __syncthreads();
    int i = blockIdx.x;
    int li = slab[i];
    float s = 0.f;
    for (int j = threadIdx.x; j < B_; j += blockDim.x) {
        if (slab[j] != li) {
            float sim = g_q[(size_t)i * B_ + j] * g_k[(size_t)i * B_ + j];
            float ca = fminf(fmaxf(sim, 0.f), 1.f);
            float sa = sqrt_approx(fminf(fmaxf(1.f - ca, 0.f), 1.f));
            float ss = sa * g_cos_apm[j] + ca * g_sin_apm[j];
            float cc = sqrt_approx(fminf(fmaxf(1.f - ss, 0.f), 1.f));
            s += exp_approx(ss * K_COSM - cc * K_SINM);
        }
    }
    s = block_sum_all(s);
    if (threadIdx.x == 0) g_nmp[i] = s;
}

// ---------- final combine ----------
__global__ void finalize_kernel(float* __restrict__ out) {
    float sa = 0.f, sn = 0.f, sm = 0.f;
    for (int j = threadIdx.x; j < B_; j += blockDim.x) {
        sa += g_aam_row[j];
        sn += g_expneg[j];
        sm += g_nmp[j];
    }
    sa = block_sum_all(sa);
    sn = block_sum_all(sn);
    sm = block_sum_all(sm);
    if (threadIdx.x == 0) {
        float aam_loss = -sa / (float)B_;
        float z = logf(sm) + logf(sn);
        float cc = fmaxf(z, 0.f) + log1pf(expf(-fabsf(z)));
        out[0] = aam_loss + cc;
    }
}

// ---------- launcher ----------
extern "C" void kernel_launch(void* const* d_in, const int* in_sizes, int n_in,
                              void* d_out, int out_size) {
    const float* x        = (const float*)d_in[0];
    const int*   label    = (const int*)d_in[1];
    const float* weight   = (const float*)d_in[2];
    const float* weight_m = (const float*)d_in[3];
    const float* weight_n = (const float*)d_in[4];
    float* out = (float*)d_out;

    __nv_bfloat16 *p_xh, *p_wh, *p_wmh, *p_wkh;
    float *p_q, *p_k;
    cudaGetSymbolAddress((void**)&p_xh,  g_xh);
    cudaGetSymbolAddress((void**)&p_wh,  g_wh);
    cudaGetSymbolAddress((void**)&p_wmh, g_wmh);
    cudaGetSymbolAddress((void**)&p_wkh, g_wkh);
    cudaGetSymbolAddress((void**)&p_q,   g_q);
    cudaGetSymbolAddress((void**)&p_k,   g_k);

    cudaFuncSetAttribute(gemm_fused_aam, cudaFuncAttributeMaxDynamicSharedMemorySize, GEMM_SMEM);
    cudaFuncSetAttribute(gemm_bf16_nt,  cudaFuncAttributeMaxDynamicSharedMemorySize, GEMM_SMEM);

    normalize_bf16_kernel<<<B_, 128>>>(x, p_xh, B_);
    normalize_bf16_kernel<<<CPAD, 128>>>(weight, p_wh, C_);   // zero-pads rows C_..CPAD
    gather_normalize_kernel<<<B_, 128>>>(weight_m, weight_n, label);

    gemm_fused_aam<<<dim3(NTC, B_ / 128), 256, GEMM_SMEM>>>(p_xh, p_wh, label);
    aam_finalize<<<B_ / 8, 256>>>(label);

    gemm_bf16_nt<<<dim3(B_ / 128, B_ / 128), 256, GEMM_SMEM>>>(p_xh, p_wmh, p_q, B_, D_);
    gemm_bf16_nt<<<dim3(B_ / 128, B_ / 128), 256, GEMM_SMEM>>>(p_xh, p_wkh, p_k, B_, D_);

    apm_kernel<<<B_, 256>>>(label);
    nm_kernel<<<B_, 256>>>(label);
    finalize_kernel<<<1, 256>>>(out);
}

// round 5
// speedup vs baseline: 5.9344x; 1.2420x over previous
#include <cuda_runtime.h>
#include <cuda_bf16.h>
#include <cuda_fp16.h>
#include <math.h>
#include <stdint.h>

#define B_ 2048
#define D_ 512
#define C_ 10000
#define CPAD 10112          // 79 * 128
#define NTC 79              // col tiles of 128
#define NPART (NTC * 2)     // partials per row

// ---------- scratch (device globals: alloc-free, capture-safe) ----------
__device__ __nv_bfloat16 g_xh[B_ * D_];
__device__ __nv_bfloat16 g_wh[(size_t)CPAD * D_];
__device__ __nv_bfloat16 g_wmh[B_ * D_];
__device__ __nv_bfloat16 g_wkh[B_ * D_];
__device__ __half g_qh[(size_t)B_ * B_];
__device__ __half g_kh[(size_t)B_ * B_];
__device__ float g_pexp[(size_t)B_ * NPART];
__device__ float g_psum[(size_t)B_ * NPART];
__device__ float g_cy[B_];
__device__ float g_aam_row[B_];
__device__ float g_expneg[B_];
__device__ float g_nmp[B_];
__device__ float g_cos_apm[B_];
__device__ float g_sin_apm[B_];

// ---------- constants ----------
constexpr float K_S    = 30.0f;
constexpr float K_COSM = 0.9800665778412416f;
constexpr float K_SINM = 0.19866933079506122f;
constexpr float K_TH   = -0.9800665778412416f;
constexpr float K_MM   = 0.039733866159012244f;
constexpr float K_EPS  = 0.1f;
constexpr float K_L2E  = 1.4426950408889634f;

// ---------- fast math (MUFU) ----------
__device__ __forceinline__ float exp_approx(float x) {
    float r;
    asm("ex2.approx.f32 %0, %1;" : "=f"(r) : "f"(x * K_L2E));
    return r;
}
__device__ __forceinline__ float sqrt_approx(float x) {
    float r;
    asm("sqrt.approx.f32 %0, %1;" : "=f"(r) : "f"(x));
    return r;
}

// ---------- block-wide sum ----------
__device__ __forceinline__ float block_sum_all(float v) {
    __shared__ float sh[33];
    int lane = threadIdx.x & 31, wid = threadIdx.x >> 5;
#pragma unroll
    for (int o = 16; o; o >>= 1) v += __shfl_down_sync(0xffffffffu, v, o);
    __syncthreads();
    if (lane == 0) sh[wid] = v;
    __syncthreads();
    if (threadIdx.x == 0) {
        float s = 0.f;
        int nw = (blockDim.x + 31) >> 5;
        for (int w = 0; w < nw; w++) s += sh[w];
        sh[32] = s;
    }
    __syncthreads();
    return sh[32];
}

// ---------- one prep kernel: w-normalize, x-normalize, gather-normalize ----------
__device__ __forceinline__ void norm_row_to(const float* src, __nv_bfloat16* dst, int t) {
    const float4 v = *(const float4*)(src + t * 4);
    float tot = block_sum_all(v.x * v.x + v.y * v.y + v.z * v.z + v.w * v.w);
    float inv = 1.0f / fmaxf(sqrtf(tot), 1e-12f);
    __nv_bfloat162* o2 = (__nv_bfloat162*)(dst + t * 4);
    o2[0] = __floats2bfloat162_rn(v.x * inv, v.y * inv);
    o2[1] = __floats2bfloat162_rn(v.z * inv, v.w * inv);
}

__global__ void prep_kernel(const float* __restrict__ x, const float* __restrict__ w,
                            const float* __restrict__ wm, const float* __restrict__ wk,
                            const int* __restrict__ label) {
    int b = blockIdx.x, t = threadIdx.x;
    if (b < CPAD) {
        __nv_bfloat16* dst = g_wh + (size_t)b * D_;
        if (b >= C_) {
            __nv_bfloat162 z = __float2bfloat162_rn(0.f);
            __nv_bfloat162* o2 = (__nv_bfloat162*)(dst + t * 4);
            o2[0] = z; o2[1] = z;
            return;
        }
        norm_row_to(w + (size_t)b * D_, dst, t);
    } else if (b < CPAD + B_) {
        int r = b - CPAD;
        norm_row_to(x + (size_t)r * D_, g_xh + (size_t)r * D_, t);
    } else {
        int i = b - CPAD - B_;
        int c = label[i];
        norm_row_to(wm + (size_t)c * D_, g_wmh + (size_t)i * D_, t);
        norm_row_to(wk + (size_t)c * D_, g_wkh + (size_t)i * D_, t);
    }
}

// ============== mma.sync bf16 building blocks ==============
__device__ __forceinline__ void ldsm4(uint32_t& r0, uint32_t& r1, uint32_t& r2, uint32_t& r3,
                                      uint32_t addr) {
    asm volatile("ldmatrix.sync.aligned.m8n8.x4.shared.b16 {%0,%1,%2,%3},[%4];\n"
                 : "=r"(r0), "=r"(r1), "=r"(r2), "=r"(r3) : "r"(addr));
}
__device__ __forceinline__ void mma16816(float* c, const uint32_t* a, uint32_t b0, uint32_t b1) {
    asm volatile("mma.sync.aligned.m16n8k16.row.col.f32.bf16.bf16.f32 "
                 "{%0,%1,%2,%3},{%4,%5,%6,%7},{%8,%9},{%0,%1,%2,%3};\n"
                 : "+f"(c[0]), "+f"(c[1]), "+f"(c[2]), "+f"(c[3])
                 : "r"(a[0]), "r"(a[1]), "r"(a[2]), "r"(a[3]), "r"(b0), "r"(b1));
}
__device__ __forceinline__ void cpasync16(uint32_t s, const void* g) {
    asm volatile("cp.async.cg.shared.global [%0],[%1],16;\n" :: "r"(s), "l"(g));
}

#define ROWB 80               // bytes per smem row (40 bf16) - conflict-free ldmatrix
#define HALFB (128 * ROWB)    // one matrix (128 rows): 10240 B
#define STAGEB (2 * HALFB)    // A + B per stage: 20480 B
#define NSTAGE 4
#define GEMM_SMEM (NSTAGE * STAGEB)   // 81920 B
#define NIT_ 16               // K = 512, 32 cols per chunk

struct TileCtx {
    uint32_t aOff[2], bOff[4];                       // ldmatrix bases (stage 0)
    uint32_t sa0, sa1, sb0, sb1;                     // cp.async smem dsts (stage 0)
    const __nv_bfloat16 *pa0, *pa1, *pb0, *pb1;      // cp.async global srcs (chunk 0)
    int wm, wn, lane;
};

__device__ __forceinline__ void tile_init(TileCtx& T, uint32_t sbase, int tid,
                                          const __nv_bfloat16* A, const __nv_bfloat16* Bm,
                                          int bm, int bn) {
    int lane = tid & 31, warp = tid >> 5;
    T.lane = lane;
    T.wm = warp >> 1; T.wn = warp & 1;
    uint32_t sA0 = sbase, sB0 = sbase + HALFB;
    int aRow = T.wm * 32 + (lane & 7) + ((lane >> 3) & 1) * 8;
    int aCol = ((lane >> 4) & 1) * 16;
    int bRow = T.wn * 64 + (lane & 7) + ((lane >> 4) & 1) * 8;
    int bCol = ((lane >> 3) & 1) * 16;
#pragma unroll
    for (int mi = 0; mi < 2; mi++) T.aOff[mi] = sA0 + (uint32_t)((aRow + mi * 16) * ROWB + aCol);
#pragma unroll
    for (int nn = 0; nn < 4; nn++) T.bOff[nn] = sB0 + (uint32_t)((bRow + nn * 16) * ROWB + bCol);
    int c0r = tid >> 2, c0k = tid & 3;
    int c1r = c0r + 64;
    T.sa0 = sA0 + c0r * ROWB + c0k * 16;
    T.sa1 = sA0 + c1r * ROWB + c0k * 16;
    T.sb0 = sB0 + c0r * ROWB + c0k * 16;
    T.sb1 = sB0 + c1r * ROWB + c0k * 16;
    T.pa0 = A + (size_t)(bm + c0r) * D_ + c0k * 8;
    T.pa1 = A + (size_t)(bm + c1r) * D_ + c0k * 8;
    T.pb0 = Bm + (size_t)(bn + c0r) * D_ + c0k * 8;
    T.pb1 = Bm + (size_t)(bn + c1r) * D_ + c0k * 8;
}

__device__ __forceinline__ void tile_load(const TileCtx& T, int stage, int k0) {
    uint32_t so = (uint32_t)(stage * STAGEB);
    cpasync16(T.sa0 + so, T.pa0 + k0);
    cpasync16(T.sa1 + so, T.pa1 + k0);
    cpasync16(T.sb0 + so, T.pb0 + k0);
    cpasync16(T.sb1 + so, T.pb1 + k0);
    asm volatile("cp.async.commit_group;\n");
}

__device__ __forceinline__ void tile_compute(const TileCtx& T, int stage, float acc[2][8][4]) {
    uint32_t soff = (uint32_t)(stage * STAGEB);
#pragma unroll
    for (int ks = 0; ks < 2; ks++) {
        uint32_t a[2][4];
        ldsm4(a[0][0], a[0][1], a[0][2], a[0][3], T.aOff[0] + soff + ks * 32);
        ldsm4(a[1][0], a[1][1], a[1][2], a[1][3], T.aOff[1] + soff + ks * 32);
        uint32_t b[8][2];
#pragma unroll
        for (int nn = 0; nn < 4; nn++) {
            uint32_t r0, r1, r2, r3;
            ldsm4(r0, r1, r2, r3, T.bOff[nn] + soff + ks * 32);
            b[2 * nn][0] = r0; b[2 * nn][1] = r1;
            b[2 * nn + 1][0] = r2; b[2 * nn + 1][1] = r3;
        }
#pragma unroll
        for (int mi = 0; mi < 2; mi++)
#pragma unroll
            for (int ni = 0; ni < 8; ni++)
                mma16816(acc[mi][ni], a[mi], b[ni][0], b[ni][1]);
    }
}

// fully unrolled 16-iter mainloop, 4 stages, tiered wait_group at the tail
__device__ __forceinline__ void gemm_mainloop512(const TileCtx& T, float acc[2][8][4]) {
    tile_load(T, 0, 0);
    tile_load(T, 1, 32);
    tile_load(T, 2, 64);
#pragma unroll
    for (int it = 0; it < NIT_; it++) {
        if (it <= NIT_ - 3)      asm volatile("cp.async.wait_group 2;\n");
        else if (it == NIT_ - 2) asm volatile("cp.async.wait_group 1;\n");
        else                     asm volatile("cp.async.wait_group 0;\n");
        __syncthreads();
        tile_compute(T, it & 3, acc);
        if (it + 3 < NIT_) tile_load(T, (it + 3) & 3, (it + 3) * 32);
    }
}

// ============== big GEMM with fused AAM epilogue (cosine never stored) ==============
__global__ void __launch_bounds__(256)
gemm_fused_aam(const __nv_bfloat16* __restrict__ A, const __nv_bfloat16* __restrict__ Bw,
               const int* __restrict__ label) {
    extern __shared__ __align__(16) char smem[];
    int tid = threadIdx.x;
    int bm = blockIdx.y * 128, bn = blockIdx.x * 128;
    TileCtx T;
    tile_init(T, (uint32_t)__cvta_generic_to_shared(smem), tid, A, Bw, bm, bn);

    float acc[2][8][4];
#pragma unroll
    for (int mi = 0; mi < 2; mi++)
#pragma unroll
        for (int ni = 0; ni < 8; ni++)
#pragma unroll
            for (int e = 0; e < 4; e++) acc[mi][ni][e] = 0.f;

    gemm_mainloop512(T, acc);

    // fused AAM epilogue: per-thread rows, quad reduce, write partials
    int lane = T.lane;
    int colbase = bn + T.wn * 64 + (lane & 3) * 2;
#pragma unroll
    for (int mi = 0; mi < 2; mi++) {
#pragma unroll
        for (int h = 0; h < 2; h++) {
            int row = bm + T.wm * 32 + mi * 16 + (lane >> 2) + h * 8;
            int lab = label[row];
            float se = 0.f, sc = 0.f, cy = 0.f;
#pragma unroll
            for (int ni = 0; ni < 8; ni++) {
                int col = colbase + ni * 8;
                float v0 = acc[mi][ni][h * 2 + 0];
                float v1 = acc[mi][ni][h * 2 + 1];
                if (col < C_) {
                    sc += v0;
                    se += exp_approx(K_S * (v0 - 1.f));
                    if (col == lab) cy = v0;
                }
                if (col + 1 < C_) {
                    sc += v1;
                    se += exp_approx(K_S * (v1 - 1.f));
                    if (col + 1 == lab) cy = v1;
                }
            }
            se += __shfl_xor_sync(0xffffffffu, se, 1);
            se += __shfl_xor_sync(0xffffffffu, se, 2);
            sc += __shfl_xor_sync(0xffffffffu, sc, 1);
            sc += __shfl_xor_sync(0xffffffffu, sc, 2);
            cy += __shfl_xor_sync(0xffffffffu, cy, 1);
            cy += __shfl_xor_sync(0xffffffffu, cy, 2);
            if ((lane & 3) == 0) {
                int part = blockIdx.x * 2 + T.wn;
                g_pexp[(size_t)row * NPART + part] = se;
                g_psum[(size_t)row * NPART + part] = sc;
                int cb = bn + T.wn * 64;
                if (lab >= cb && lab < cb + 64) g_cy[row] = cy;
            }
        }
    }
}

// ============== plain GEMM (q, k): stores fp16 C ==============
__global__ void __launch_bounds__(256)
gemm_bf16_nt_h(const __nv_bfloat16* __restrict__ A, const __nv_bfloat16* __restrict__ Bm,
               __half* __restrict__ Cm) {
    extern __shared__ __align__(16) char smem[];
    int tid = threadIdx.x;
    int bm = blockIdx.y * 128, bn = blockIdx.x * 128;
    TileCtx T;
    tile_init(T, (uint32_t)__cvta_generic_to_shared(smem), tid, A, Bm, bm, bn);

    float acc[2][8][4];
#pragma unroll
    for (int mi = 0; mi < 2; mi++)
#pragma unroll
        for (int ni = 0; ni < 8; ni++)
#pragma unroll
            for (int e = 0; e < 4; e++) acc[mi][ni][e] = 0.f;

    gemm_mainloop512(T, acc);

    int lane = T.lane;
#pragma unroll
    for (int mi = 0; mi < 2; mi++) {
        int r0 = bm + T.wm * 32 + mi * 16 + (lane >> 2);
#pragma unroll
        for (int ni = 0; ni < 8; ni++) {
            int c0 = bn + T.wn * 64 + ni * 8 + (lane & 3) * 2;
            *(__half2*)(Cm + (size_t)r0 * B_ + c0) =
                __floats2half2_rn(acc[mi][ni][0], acc[mi][ni][1]);
            *(__half2*)(Cm + (size_t)(r0 + 8) * B_ + c0) =
                __floats2half2_rn(acc[mi][ni][2], acc[mi][ni][3]);
        }
    }
}

// ---------- AAM per-row finalize (warp per row) ----------
__global__ void aam_finalize(const int* __restrict__ label) {
    int row = blockIdx.x * 8 + (threadIdx.x >> 5);
    int lane = threadIdx.x & 31;
    float se = 0.f, sc = 0.f;
    for (int j = lane; j < NPART; j += 32) {
        se += g_pexp[(size_t)row * NPART + j];
        sc += g_psum[(size_t)row * NPART + j];
    }
#pragma unroll
    for (int o = 16; o; o >>= 1) {
        se += __shfl_down_sync(0xffffffffu, se, o);
        sc += __shfl_down_sync(0xffffffffu, sc, o);
    }
    if (lane == 0) {
        float cyv = g_cy[row];
        float sine = sqrtf(fminf(fmaxf(1.f - cyv * cyv, 0.f), 1.f));
        float phi = cyv * K_COSM - sine * K_SINM;
        phi = (cyv - K_TH > 0.f) ? phi : (cyv - K_MM);
        float oy = K_S * phi, ocy = K_S * cyv;
        float sout = K_S * sc + (oy - ocy);
        se += expf(oy - K_S) - expf(ocy - K_S);
        float lse = K_S + logf(se);
        g_aam_row[row] = (1.f - K_EPS) * (oy - lse) + (K_EPS / C_) * sout - K_EPS * lse;
    }
}

// ---------- ap_m / ap / exp(logit_neg): half2 reads, label-gated ----------
__global__ void apm_kernel(const int* __restrict__ label) {
    __shared__ int slab[B_];
    for (int j = threadIdx.x; j < B_; j += blockDim.x) slab[j] = label[j];
    __syncthreads();
    int i = blockIdx.x;
    int li = slab[i];
    const __half2* q2 = (const __half2*)(g_qh + (size_t)i * B_);
    const __half2* k2 = (const __half2*)(g_kh + (size_t)i * B_);
    float ssum = 0.f, cnt = 0.f;
    for (int j2 = threadIdx.x; j2 < B_ / 2; j2 += blockDim.x) {
        int j0 = j2 * 2;
        if (slab[j0] == li || slab[j0 + 1] == li) {
            float2 qv = __half22float2(q2[j2]);
            float2 kv = __half22float2(k2[j2]);
            if (slab[j0] == li)     { ssum += qv.x * kv.x; cnt += 1.f; }
            if (slab[j0 + 1] == li) { ssum += qv.y * kv.y; cnt += 1.f; }
        }
    }
    ssum = block_sum_all(ssum);
    cnt  = block_sum_all(cnt);
    if (threadIdx.x == 0) {
        float apm = ssum / cnt;
        float ap  = __half2float(g_qh[(size_t)i * B_ + i]) * __half2float(g_kh[(size_t)i * B_ + i]);
        float cos_ap  = fminf(fmaxf(ap, 0.f), 1.f);
        float sin_ap  = sqrt_approx(fminf(fmaxf(1.f - cos_ap, 0.f), 1.f));
        float cos_apm = fminf(fmaxf(apm, 0.f), 1.f);
        float sin_apm = sqrt_approx(fminf(fmaxf(1.f - cos_apm, 0.f), 1.f));
        g_cos_apm[i] = cos_apm;
        g_sin_apm[i] = sin_apm;
        float pc = cos_ap * cos_apm - sin_ap * sin_apm;
        float ps = sqrt_approx(fminf(fmaxf(1.f - pc, 0.f), 1.f));
        float phi_pm = pc * K_COSM - ps * K_SINM;
        g_expneg[i] = exp_approx(1.f - phi_pm);
    }
}

// ---------- masked sum of exp(phi_nm) per row ----------
__device__ __forceinline__ float nm_term(float sim, float capm, float sapm) {
    float ca = fminf(fmaxf(sim, 0.f), 1.f);
    float sa = sqrt_approx(fminf(fmaxf(1.f - ca, 0.f), 1.f));
    float ss = sa * capm + ca * sapm;
    float cc = sqrt_approx(fminf(fmaxf(1.f - ss, 0.f), 1.f));
    return exp_approx(ss * K_COSM - cc * K_SINM);
}

__global__ void nm_kernel(const int* __restrict__ label) {
    __shared__ int slab[B_];
    for (int j = threadIdx.x; j < B_; j += blockDim.x) slab[j] = label[j];
    __syncthreads();
    int i = blockIdx.x;
    int li = slab[i];
    const __half2* q2 = (const __half2*)(g_qh + (size_t)i * B_);
    const __half2* k2 = (const __half2*)(g_kh + (size_t)i * B_);
    float s = 0.f;
    for (int j2 = threadIdx.x; j2 < B_ / 2; j2 += blockDim.x) {
        int j0 = j2 * 2;
        float2 qv = __half22float2(q2[j2]);
        float2 kv = __half22float2(k2[j2]);
        if (slab[j0] != li)     s += nm_term(qv.x * kv.x, g_cos_apm[j0], g_sin_apm[j0]);
        if (slab[j0 + 1] != li) s += nm_term(qv.y * kv.y, g_cos_apm[j0 + 1], g_sin_apm[j0 + 1]);
    }
    s = block_sum_all(s);
    if (threadIdx.x == 0) g_nmp[i] = s;
}

// ---------- final combine ----------
__global__ void finalize_kernel(float* __restrict__ out) {
    float sa = 0.f, sn = 0.f, sm = 0.f;
    for (int j = threadIdx.x; j < B_; j += blockDim.x) {
        sa += g_aam_row[j];
        sn += g_expneg[j];
        sm += g_nmp[j];
    }
    sa = block_sum_all(sa);
    sn = block_sum_all(sn);
    sm = block_sum_all(sm);
    if (threadIdx.x == 0) {
        float aam_loss = -sa / (float)B_;
        float z = logf(sm) + logf(sn);
        float cc = fmaxf(z, 0.f) + log1pf(expf(-fabsf(z)));
        out[0] = aam_loss + cc;
    }
}

// ---------- launcher ----------
extern "C" void kernel_launch(void* const* d_in, const int* in_sizes, int n_in,
                              void* d_out, int out_size) {
    const float* x        = (const float*)d_in[0];
    const int*   label    = (const int*)d_in[1];
    const float* weight   = (const float*)d_in[2];
    const float* weight_m = (const float*)d_in[3];
    const float* weight_n = (const float*)d_in[4];
    float* out = (float*)d_out;

    __nv_bfloat16 *p_xh, *p_wh, *p_wmh, *p_wkh;
    __half *p_qh, *p_kh;
    cudaGetSymbolAddress((void**)&p_xh,  g_xh);
    cudaGetSymbolAddress((void**)&p_wh,  g_wh);
    cudaGetSymbolAddress((void**)&p_wmh, g_wmh);
    cudaGetSymbolAddress((void**)&p_wkh, g_wkh);
    cudaGetSymbolAddress((void**)&p_qh,  g_qh);
    cudaGetSymbolAddress((void**)&p_kh,  g_kh);

    cudaFuncSetAttribute(gemm_fused_aam, cudaFuncAttributeMaxDynamicSharedMemorySize, GEMM_SMEM);
    cudaFuncSetAttribute(gemm_bf16_nt_h, cudaFuncAttributeMaxDynamicSharedMemorySize, GEMM_SMEM);

    prep_kernel<<<CPAD + B_ + B_, 128>>>(x, weight, weight_m, weight_n, label);

    gemm_fused_aam<<<dim3(NTC, B_ / 128), 256, GEMM_SMEM>>>(p_xh, p_wh, label);
    aam_finalize<<<B_ / 8, 256>>>(label);

    gemm_bf16_nt_h<<<dim3(B_ / 128, B_ / 128), 256, GEMM_SMEM>>>(p_xh, p_wmh, p_qh);
    gemm_bf16_nt_h<<<dim3(B_ / 128, B_ / 128), 256, GEMM_SMEM>>>(p_xh, p_wkh, p_kh);

    apm_kernel<<<B_, 256>>>(label);
    nm_kernel<<<B_, 256>>>(label);
    finalize_kernel<<<1, 256>>>(out);
}

// round 6
// speedup vs baseline: 6.1177x; 1.0309x over previous
#include <cuda_runtime.h>
#include <cuda_bf16.h>
#include <cuda_fp16.h>
#include <math.h>
#include <stdint.h>

#define B_ 2048
#define D_ 512
#define C_ 10000
#define CPAD 10112          // 79 * 128
#define NTC 79              // col tiles of 128 (AAM)
#define NPART (NTC * 2)     // AAM partials per row
#define NQT 16              // col tiles of 128 (B x B)
#define NPARTQ (NQT * 2)    // nm partials per row

// ---------- scratch (device globals: alloc-free, capture-safe) ----------
__device__ __nv_bfloat16 g_xh[B_ * D_];
__device__ __nv_bfloat16 g_wh[(size_t)CPAD * D_];
__device__ __nv_bfloat16 g_wmh[B_ * D_];
__device__ __nv_bfloat16 g_wkh[B_ * D_];
__device__ __half g_qh[(size_t)B_ * B_];
__device__ float g_pexp[(size_t)B_ * NPART];
__device__ float g_psum[(size_t)B_ * NPART];
__device__ float g_nm_p[(size_t)B_ * NPARTQ];
__device__ float g_cy[B_];
__device__ float g_aam_row[B_];
__device__ float g_expneg[B_];
__device__ float g_nmp[B_];
__device__ float g_cos_apm[B_];
__device__ float g_sin_apm[B_];

// ---------- constants ----------
constexpr float K_S    = 30.0f;
constexpr float K_COSM = 0.9800665778412416f;
constexpr float K_SINM = 0.19866933079506122f;
constexpr float K_TH   = -0.9800665778412416f;
constexpr float K_MM   = 0.039733866159012244f;
constexpr float K_EPS  = 0.1f;
constexpr float K_L2E  = 1.4426950408889634f;

// ---------- fast math (MUFU) ----------
__device__ __forceinline__ float exp_approx(float x) {
    float r;
    asm("ex2.approx.f32 %0, %1;" : "=f"(r) : "f"(x * K_L2E));
    return r;
}
__device__ __forceinline__ float sqrt_approx(float x) {
    float r;
    asm("sqrt.approx.f32 %0, %1;" : "=f"(r) : "f"(x));
    return r;
}

// ---------- block-wide sum ----------
__device__ __forceinline__ float block_sum_all(float v) {
    __shared__ float sh[33];
    int lane = threadIdx.x & 31, wid = threadIdx.x >> 5;
#pragma unroll
    for (int o = 16; o; o >>= 1) v += __shfl_down_sync(0xffffffffu, v, o);
    __syncthreads();
    if (lane == 0) sh[wid] = v;
    __syncthreads();
    if (threadIdx.x == 0) {
        float s = 0.f;
        int nw = (blockDim.x + 31) >> 5;
        for (int w = 0; w < nw; w++) s += sh[w];
        sh[32] = s;
    }
    __syncthreads();
    return sh[32];
}

// ---------- prep: normalize everything -> bf16 ----------
__device__ __forceinline__ void norm_row_to(const float* src, __nv_bfloat16* dst, int t) {
    const float4 v = *(const float4*)(src + t * 4);
    float tot = block_sum_all(v.x * v.x + v.y * v.y + v.z * v.z + v.w * v.w);
    float inv = 1.0f / fmaxf(sqrtf(tot), 1e-12f);
    __nv_bfloat162* o2 = (__nv_bfloat162*)(dst + t * 4);
    o2[0] = __floats2bfloat162_rn(v.x * inv, v.y * inv);
    o2[1] = __floats2bfloat162_rn(v.z * inv, v.w * inv);
}

__global__ void prep_kernel(const float* __restrict__ x, const float* __restrict__ w,
                            const float* __restrict__ wm, const float* __restrict__ wk,
                            const int* __restrict__ label) {
    int b = blockIdx.x, t = threadIdx.x;
    if (b < CPAD) {
        __nv_bfloat16* dst = g_wh + (size_t)b * D_;
        if (b >= C_) {
            __nv_bfloat162 z = __float2bfloat162_rn(0.f);
            __nv_bfloat162* o2 = (__nv_bfloat162*)(dst + t * 4);
            o2[0] = z; o2[1] = z;
            return;
        }
        norm_row_to(w + (size_t)b * D_, dst, t);
    } else if (b < CPAD + B_) {
        int r = b - CPAD;
        norm_row_to(x + (size_t)r * D_, g_xh + (size_t)r * D_, t);
    } else {
        int i = b - CPAD - B_;
        int c = label[i];
        norm_row_to(wm + (size_t)c * D_, g_wmh + (size_t)i * D_, t);
        norm_row_to(wk + (size_t)c * D_, g_wkh + (size_t)i * D_, t);
    }
}

// ---------- apm from label-matching pairs only (~2 per row): direct dots ----------
__global__ void __launch_bounds__(256)
apm_pairs_kernel(const int* __restrict__ label) {
    __shared__ int slab[B_];
    __shared__ int mlist[64];
    __shared__ int mcnt_s;
    __shared__ int wcnt[8], woff[8];
    int i = blockIdx.x, t = threadIdx.x;
    for (int j = t; j < B_; j += 256) slab[j] = label[j];
    if (t == 0) mcnt_s = 0;
    __syncthreads();
    int li = slab[i];
    // ordered match-list build
    for (int base = 0; base < B_; base += 256) {
        int j = base + t;
        bool m = (slab[j] == li);
        unsigned bal = __ballot_sync(0xffffffffu, m);
        int lane = t & 31, w = t >> 5;
        if (lane == 0) wcnt[w] = __popc(bal);
        __syncthreads();
        if (t == 0) {
            int off = mcnt_s;
            for (int ww = 0; ww < 8; ww++) { woff[ww] = off; off += wcnt[ww]; }
            mcnt_s = off;
        }
        __syncthreads();
        if (m) {
            int pos = woff[w] + __popc(bal & ((1u << lane) - 1u));
            if (pos < 64) mlist[pos] = j;
        }
        __syncthreads();
    }
    int cnt = mcnt_s < 64 ? mcnt_s : 64;
    // xn_i dims 2t, 2t+1
    float x0 = __bfloat162float(g_xh[(size_t)i * D_ + 2 * t]);
    float x1 = __bfloat162float(g_xh[(size_t)i * D_ + 2 * t + 1]);
    float ssum = 0.f, ap = 0.f;
    for (int m = 0; m < cnt; m++) {
        int j = mlist[m];
        float q0 = __bfloat162float(g_wmh[(size_t)j * D_ + 2 * t]);
        float q1 = __bfloat162float(g_wmh[(size_t)j * D_ + 2 * t + 1]);
        float k0 = __bfloat162float(g_wkh[(size_t)j * D_ + 2 * t]);
        float k1 = __bfloat162float(g_wkh[(size_t)j * D_ + 2 * t + 1]);
        float dq = block_sum_all(x0 * q0 + x1 * q1);
        float dk = block_sum_all(x0 * k0 + x1 * k1);
        float sim = dq * dk;
        ssum += sim;
        if (j == i) ap = sim;
    }
    if (t == 0) {
        float apm = ssum / (float)cnt;                  // diagonal always matches -> cnt >= 1
        float cos_ap  = fminf(fmaxf(ap, 0.f), 1.f);
        float sin_ap  = sqrt_approx(fminf(fmaxf(1.f - cos_ap, 0.f), 1.f));
        float cos_apm = fminf(fmaxf(apm, 0.f), 1.f);
        float sin_apm = sqrt_approx(fminf(fmaxf(1.f - cos_apm, 0.f), 1.f));
        g_cos_apm[i] = cos_apm;
        g_sin_apm[i] = sin_apm;
        float pc = cos_ap * cos_apm - sin_ap * sin_apm;
        float ps = sqrt_approx(fminf(fmaxf(1.f - pc, 0.f), 1.f));
        float phi_pm = pc * K_COSM - ps * K_SINM;
        g_expneg[i] = exp_approx(1.f - phi_pm);
    }
}

// ============== mma.sync bf16 building blocks ==============
__device__ __forceinline__ void ldsm4(uint32_t& r0, uint32_t& r1, uint32_t& r2, uint32_t& r3,
                                      uint32_t addr) {
    asm volatile("ldmatrix.sync.aligned.m8n8.x4.shared.b16 {%0,%1,%2,%3},[%4];\n"
                 : "=r"(r0), "=r"(r1), "=r"(r2), "=r"(r3) : "r"(addr));
}
__device__ __forceinline__ void mma16816(float* c, const uint32_t* a, uint32_t b0, uint32_t b1) {
    asm volatile("mma.sync.aligned.m16n8k16.row.col.f32.bf16.bf16.f32 "
                 "{%0,%1,%2,%3},{%4,%5,%6,%7},{%8,%9},{%0,%1,%2,%3};\n"
                 : "+f"(c[0]), "+f"(c[1]), "+f"(c[2]), "+f"(c[3])
                 : "r"(a[0]), "r"(a[1]), "r"(a[2]), "r"(a[3]), "r"(b0), "r"(b1));
}
__device__ __forceinline__ void cpasync16(uint32_t s, const void* g) {
    asm volatile("cp.async.cg.shared.global [%0],[%1],16;\n" :: "r"(s), "l"(g));
}

#define ROWB 80
#define HALFB (128 * ROWB)
#define STAGEB (2 * HALFB)
#define NSTAGE 4
#define GEMM_SMEM (NSTAGE * STAGEB)   // 81920 B
#define NIT_ 16

struct TileCtx {
    uint32_t aOff[2], bOff[4];
    uint32_t sa0, sa1, sb0, sb1;
    const __nv_bfloat16 *pa0, *pa1, *pb0, *pb1;
    int wm, wn, lane;
};

__device__ __forceinline__ void tile_init(TileCtx& T, uint32_t sbase, int tid,
                                          const __nv_bfloat16* A, const __nv_bfloat16* Bm,
                                          int bm, int bn) {
    int lane = tid & 31, warp = tid >> 5;
    T.lane = lane;
    T.wm = warp >> 1; T.wn = warp & 1;
    uint32_t sA0 = sbase, sB0 = sbase + HALFB;
    int aRow = T.wm * 32 + (lane & 7) + ((lane >> 3) & 1) * 8;
    int aCol = ((lane >> 4) & 1) * 16;
    int bRow = T.wn * 64 + (lane & 7) + ((lane >> 4) & 1) * 8;
    int bCol = ((lane >> 3) & 1) * 16;
#pragma unroll
    for (int mi = 0; mi < 2; mi++) T.aOff[mi] = sA0 + (uint32_t)((aRow + mi * 16) * ROWB + aCol);
#pragma unroll
    for (int nn = 0; nn < 4; nn++) T.bOff[nn] = sB0 + (uint32_t)((bRow + nn * 16) * ROWB + bCol);
    int c0r = tid >> 2, c0k = tid & 3;
    int c1r = c0r + 64;
    T.sa0 = sA0 + c0r * ROWB + c0k * 16;
    T.sa1 = sA0 + c1r * ROWB + c0k * 16;
    T.sb0 = sB0 + c0r * ROWB + c0k * 16;
    T.sb1 = sB0 + c1r * ROWB + c0k * 16;
    T.pa0 = A + (size_t)(bm + c0r) * D_ + c0k * 8;
    T.pa1 = A + (size_t)(bm + c1r) * D_ + c0k * 8;
    T.pb0 = Bm + (size_t)(bn + c0r) * D_ + c0k * 8;
    T.pb1 = Bm + (size_t)(bn + c1r) * D_ + c0k * 8;
}

__device__ __forceinline__ void tile_load(const TileCtx& T, int stage, int k0) {
    uint32_t so = (uint32_t)(stage * STAGEB);
    cpasync16(T.sa0 + so, T.pa0 + k0);
    cpasync16(T.sa1 + so, T.pa1 + k0);
    cpasync16(T.sb0 + so, T.pb0 + k0);
    cpasync16(T.sb1 + so, T.pb1 + k0);
    asm volatile("cp.async.commit_group;\n");
}

__device__ __forceinline__ void tile_compute(const TileCtx& T, int stage, float acc[2][8][4]) {
    uint32_t soff = (uint32_t)(stage * STAGEB);
#pragma unroll
    for (int ks = 0; ks < 2; ks++) {
        uint32_t a[2][4];
        ldsm4(a[0][0], a[0][1], a[0][2], a[0][3], T.aOff[0] + soff + ks * 32);
        ldsm4(a[1][0], a[1][1], a[1][2], a[1][3], T.aOff[1] + soff + ks * 32);
        uint32_t b[8][2];
#pragma unroll
        for (int nn = 0; nn < 4; nn++) {
            uint32_t r0, r1, r2, r3;
            ldsm4(r0, r1, r2, r3, T.bOff[nn] + soff + ks * 32);
            b[2 * nn][0] = r0; b[2 * nn][1] = r1;
            b[2 * nn + 1][0] = r2; b[2 * nn + 1][1] = r3;
        }
#pragma unroll
        for (int mi = 0; mi < 2; mi++)
#pragma unroll
            for (int ni = 0; ni < 8; ni++)
                mma16816(acc[mi][ni], a[mi], b[ni][0], b[ni][1]);
    }
}

__device__ __forceinline__ void gemm_mainloop512(const TileCtx& T, float acc[2][8][4]) {
    tile_load(T, 0, 0);
    tile_load(T, 1, 32);
    tile_load(T, 2, 64);
#pragma unroll
    for (int it = 0; it < NIT_; it++) {
        if (it <= NIT_ - 3)      asm volatile("cp.async.wait_group 2;\n");
        else if (it == NIT_ - 2) asm volatile("cp.async.wait_group 1;\n");
        else                     asm volatile("cp.async.wait_group 0;\n");
        __syncthreads();
        tile_compute(T, it & 3, acc);
        if (it + 3 < NIT_) tile_load(T, (it + 3) & 3, (it + 3) * 32);
    }
}

#define ACC_INIT(acc) do {                                                \
    _Pragma("unroll") for (int mi = 0; mi < 2; mi++)                      \
    _Pragma("unroll") for (int ni = 0; ni < 8; ni++)                      \
    _Pragma("unroll") for (int e = 0; e < 4; e++) acc[mi][ni][e] = 0.f;   \
} while (0)

// ============== AAM GEMM with fused epilogue (cosine never stored) ==============
__global__ void __launch_bounds__(256)
gemm_fused_aam(const __nv_bfloat16* __restrict__ A, const __nv_bfloat16* __restrict__ Bw,
               const int* __restrict__ label) {
    extern __shared__ __align__(16) char smem[];
    int tid = threadIdx.x;
    int bm = blockIdx.y * 128, bn = blockIdx.x * 128;
    TileCtx T;
    tile_init(T, (uint32_t)__cvta_generic_to_shared(smem), tid, A, Bw, bm, bn);
    float acc[2][8][4];
    ACC_INIT(acc);
    gemm_mainloop512(T, acc);

    int lane = T.lane;
    int colbase = bn + T.wn * 64 + (lane & 3) * 2;
#pragma unroll
    for (int mi = 0; mi < 2; mi++) {
#pragma unroll
        for (int h = 0; h < 2; h++) {
            int row = bm + T.wm * 32 + mi * 16 + (lane >> 2) + h * 8;
            int lab = label[row];
            float se = 0.f, sc = 0.f, cy = 0.f;
#pragma unroll
            for (int ni = 0; ni < 8; ni++) {
                int col = colbase + ni * 8;
                float v0 = acc[mi][ni][h * 2 + 0];
                float v1 = acc[mi][ni][h * 2 + 1];
                if (col < C_) {
                    sc += v0;
                    se += exp_approx(K_S * (v0 - 1.f));
                    if (col == lab) cy = v0;
                }
                if (col + 1 < C_) {
                    sc += v1;
                    se += exp_approx(K_S * (v1 - 1.f));
                    if (col + 1 == lab) cy = v1;
                }
            }
            se += __shfl_xor_sync(0xffffffffu, se, 1);
            se += __shfl_xor_sync(0xffffffffu, se, 2);
            sc += __shfl_xor_sync(0xffffffffu, sc, 1);
            sc += __shfl_xor_sync(0xffffffffu, sc, 2);
            cy += __shfl_xor_sync(0xffffffffu, cy, 1);
            cy += __shfl_xor_sync(0xffffffffu, cy, 2);
            if ((lane & 3) == 0) {
                int part = blockIdx.x * 2 + T.wn;
                g_pexp[(size_t)row * NPART + part] = se;
                g_psum[(size_t)row * NPART + part] = sc;
                int cb = bn + T.wn * 64;
                if (lab >= cb && lab < cb + 64) g_cy[row] = cy;
            }
        }
    }
}

// ============== q GEMM: stores fp16 q ==============
__global__ void __launch_bounds__(256)
gemm_q(const __nv_bfloat16* __restrict__ A, const __nv_bfloat16* __restrict__ Bm,
       __half* __restrict__ Cm) {
    extern __shared__ __align__(16) char smem[];
    int tid = threadIdx.x;
    int bm = blockIdx.y * 128, bn = blockIdx.x * 128;
    TileCtx T;
    tile_init(T, (uint32_t)__cvta_generic_to_shared(smem), tid, A, Bm, bm, bn);
    float acc[2][8][4];
    ACC_INIT(acc);
    gemm_mainloop512(T, acc);

    int lane = T.lane;
#pragma unroll
    for (int mi = 0; mi < 2; mi++) {
        int r0 = bm + T.wm * 32 + mi * 16 + (lane >> 2);
#pragma unroll
        for (int ni = 0; ni < 8; ni++) {
            int c0 = bn + T.wn * 64 + ni * 8 + (lane & 3) * 2;
            *(__half2*)(Cm + (size_t)r0 * B_ + c0) =
                __floats2half2_rn(acc[mi][ni][0], acc[mi][ni][1]);
            *(__half2*)(Cm + (size_t)(r0 + 8) * B_ + c0) =
                __floats2half2_rn(acc[mi][ni][2], acc[mi][ni][3]);
        }
    }
}

// ---------- nm term ----------
__device__ __forceinline__ float nm_term(float sim, float capm, float sapm) {
    float ca = fminf(fmaxf(sim, 0.f), 1.f);
    float sa = sqrt_approx(fminf(fmaxf(1.f - ca, 0.f), 1.f));
    float ss = sa * capm + ca * sapm;
    float cc = sqrt_approx(fminf(fmaxf(1.f - ss, 0.f), 1.f));
    return exp_approx(ss * K_COSM - cc * K_SINM);
}

// ============== k GEMM + fused nm epilogue (k and sim never stored) ==============
__global__ void __launch_bounds__(256)
gemm_k_nm(const __nv_bfloat16* __restrict__ A, const __nv_bfloat16* __restrict__ Bm,
          const __half* __restrict__ Q, const int* __restrict__ label) {
    extern __shared__ __align__(16) char smem[];
    int tid = threadIdx.x;
    int bm = blockIdx.y * 128, bn = blockIdx.x * 128;
    TileCtx T;
    tile_init(T, (uint32_t)__cvta_generic_to_shared(smem), tid, A, Bm, bm, bn);
    float acc[2][8][4];
    ACC_INIT(acc);
    gemm_mainloop512(T, acc);

    // epilogue scratch in smem (mainloop fully consumed after last tile_compute)
    __syncthreads();
    float* s_capm = (float*)smem;            // [128]
    float* s_sapm = s_capm + 128;            // [128]
    int*   s_lcol = (int*)(s_sapm + 128);    // [128]
    int*   s_lrow = s_lcol + 128;            // [128]
    if (tid < 128) {
        s_capm[tid] = g_cos_apm[bn + tid];
        s_sapm[tid] = g_sin_apm[bn + tid];
        s_lcol[tid] = label[bn + tid];
    } else {
        s_lrow[tid - 128] = label[bm + tid - 128];
    }
    __syncthreads();

    int lane = T.lane;
    int colloc0 = T.wn * 64 + (lane & 3) * 2;
#pragma unroll
    for (int mi = 0; mi < 2; mi++) {
#pragma unroll
        for (int h = 0; h < 2; h++) {
            int rloc = T.wm * 32 + mi * 16 + (lane >> 2) + h * 8;
            int row = bm + rloc;
            int lrow = s_lrow[rloc];
            float s = 0.f;
#pragma unroll
            for (int ni = 0; ni < 8; ni++) {
                int cl = colloc0 + ni * 8;
                __half2 q2 = *(const __half2*)(Q + (size_t)row * B_ + bn + cl);
                float2 qv = __half22float2(q2);
                float k0 = acc[mi][ni][h * 2 + 0];
                float k1 = acc[mi][ni][h * 2 + 1];
                if (s_lcol[cl] != lrow)     s += nm_term(qv.x * k0, s_capm[cl], s_sapm[cl]);
                if (s_lcol[cl + 1] != lrow) s += nm_term(qv.y * k1, s_capm[cl + 1], s_sapm[cl + 1]);
            }
            s += __shfl_xor_sync(0xffffffffu, s, 1);
            s += __shfl_xor_sync(0xffffffffu, s, 2);
            if ((lane & 3) == 0)
                g_nm_p[(size_t)row * NPARTQ + blockIdx.x * 2 + T.wn] = s;
        }
    }
}

// ---------- merged row finalize: aam rows + nm rows ----------
__global__ void finalize_rows(const int* __restrict__ label) {
    int w = threadIdx.x >> 5, lane = threadIdx.x & 31;
    if (blockIdx.x < B_ / 8) {
        int row = blockIdx.x * 8 + w;
        float se = 0.f, sc = 0.f;
        for (int j = lane; j < NPART; j += 32) {
            se += g_pexp[(size_t)row * NPART + j];
            sc += g_psum[(size_t)row * NPART + j];
        }
#pragma unroll
        for (int o = 16; o; o >>= 1) {
            se += __shfl_down_sync(0xffffffffu, se, o);
            sc += __shfl_down_sync(0xffffffffu, sc, o);
        }
        if (lane == 0) {
            float cyv = g_cy[row];
            float sine = sqrtf(fminf(fmaxf(1.f - cyv * cyv, 0.f), 1.f));
            float phi = cyv * K_COSM - sine * K_SINM;
            phi = (cyv - K_TH > 0.f) ? phi : (cyv - K_MM);
            float oy = K_S * phi, ocy = K_S * cyv;
            float sout = K_S * sc + (oy - ocy);
            se += expf(oy - K_S) - expf(ocy - K_S);
            float lse = K_S + logf(se);
            g_aam_row[row] = (1.f - K_EPS) * (oy - lse) + (K_EPS / C_) * sout - K_EPS * lse;
        }
    } else {
        int row = (blockIdx.x - B_ / 8) * 8 + w;
        float s = g_nm_p[(size_t)row * NPARTQ + lane];   // NPARTQ == 32
#pragma unroll
        for (int o = 16; o; o >>= 1) s += __shfl_down_sync(0xffffffffu, s, o);
        if (lane == 0) g_nmp[row] = s;
    }
}

// ---------- final combine ----------
__global__ void final_combine(float* __restrict__ out) {
    float sa = 0.f, sn = 0.f, sm = 0.f;
    for (int j = threadIdx.x; j < B_; j += blockDim.x) {
        sa += g_aam_row[j];
        sn += g_expneg[j];
        sm += g_nmp[j];
    }
    sa = block_sum_all(sa);
    sn = block_sum_all(sn);
    sm = block_sum_all(sm);
    if (threadIdx.x == 0) {
        float aam_loss = -sa / (float)B_;
        float z = logf(sm) + logf(sn);
        float cc = fmaxf(z, 0.f) + log1pf(expf(-fabsf(z)));
        out[0] = aam_loss + cc;
    }
}

// ---------- launcher: fork qk chain onto a second stream during capture ----------
extern "C" void kernel_launch(void* const* d_in, const int* in_sizes, int n_in,
                              void* d_out, int out_size) {
    const float* x        = (const float*)d_in[0];
    const int*   label    = (const int*)d_in[1];
    const float* weight   = (const float*)d_in[2];
    const float* weight_m = (const float*)d_in[3];
    const float* weight_n = (const float*)d_in[4];
    float* out = (float*)d_out;

    __nv_bfloat16 *p_xh, *p_wh, *p_wmh, *p_wkh;
    __half *p_qh;
    cudaGetSymbolAddress((void**)&p_xh,  g_xh);
    cudaGetSymbolAddress((void**)&p_wh,  g_wh);
    cudaGetSymbolAddress((void**)&p_wmh, g_wmh);
    cudaGetSymbolAddress((void**)&p_wkh, g_wkh);
    cudaGetSymbolAddress((void**)&p_qh,  g_qh);

    cudaFuncSetAttribute(gemm_fused_aam, cudaFuncAttributeMaxDynamicSharedMemorySize, GEMM_SMEM);
    cudaFuncSetAttribute(gemm_q,         cudaFuncAttributeMaxDynamicSharedMemorySize, GEMM_SMEM);
    cudaFuncSetAttribute(gemm_k_nm,      cudaFuncAttributeMaxDynamicSharedMemorySize, GEMM_SMEM);

    cudaStream_t s1 = 0;
    cudaEvent_t evA = 0, evB = 0;
    bool forked = (cudaStreamCreateWithFlags(&s1, cudaStreamNonBlocking) == cudaSuccess) &&
                  (cudaEventCreateWithFlags(&evA, cudaEventDisableTiming) == cudaSuccess) &&
                  (cudaEventCreateWithFlags(&evB, cudaEventDisableTiming) == cudaSuccess);
    if (!forked) s1 = 0;

    prep_kernel<<<CPAD + B_ + B_, 128>>>(x, weight, weight_m, weight_n, label);

    if (forked) {
        cudaEventRecord(evA, 0);
        cudaStreamWaitEvent(s1, evA, 0);
    }
    // contrastive chain (stream s1)
    apm_pairs_kernel<<<B_, 256, 0, s1>>>(label);
    gemm_q<<<dim3(NQT, B_ / 128), 256, GEMM_SMEM, s1>>>(p_xh, p_wmh, p_qh);
    gemm_k_nm<<<dim3(NQT, B_ / 128), 256, GEMM_SMEM, s1>>>(p_xh, p_wkh, p_qh, label);
    if (forked) cudaEventRecord(evB, s1);

    // AAM chain (stream 0) runs concurrently
    gemm_fused_aam<<<dim3(NTC, B_ / 128), 256, GEMM_SMEM>>>(p_xh, p_wh, label);

    if (forked) cudaStreamWaitEvent(0, evB, 0);
    finalize_rows<<<2 * (B_ / 8), 256>>>(label);
    final_combine<<<1, 256>>>(out);
    // note: stream/events intentionally not destroyed (illegal while capture is
    // active; a few leaked host handles across harness calls, no device memory)
}

// round 7
// speedup vs baseline: 6.7497x; 1.1033x over previous
#include <cuda_runtime.h>
#include <cuda_bf16.h>
#include <math.h>
#include <stdint.h>

#define B_ 2048
#define D_ 512
#define C_ 10000
#define CPAD 10112          // 79 * 128
#define NTC 79              // AAM col tiles of 128
#define NPART (NTC * 2)     // AAM partials per row
#define NQCT 32             // QK col tiles of 64
#define NPARTQ (NQCT * 2)   // nm partials per row (2 warp col-halves per 64)
#define NAAMBLK (NTC * (B_ / 128))        // 1264
#define NQKBLK  (NQCT * (B_ / 128))       // 512

// ---------- scratch (device globals: alloc-free, capture-safe) ----------
__device__ __nv_bfloat16 g_xh[B_ * D_];
__device__ __nv_bfloat16 g_wh[(size_t)CPAD * D_];
__device__ __nv_bfloat16 g_wmh[B_ * D_];
__device__ __nv_bfloat16 g_wkh[B_ * D_];
__device__ float g_pexp[(size_t)B_ * NPART];
__device__ float g_psum[(size_t)B_ * NPART];
__device__ float g_nm_p[(size_t)B_ * NPARTQ];
__device__ float g_cy[B_];
__device__ float g_aam_row[B_];
__device__ float g_expneg[B_];
__device__ float g_nmp[B_];
__device__ float g_cos_apm[B_];
__device__ float g_sin_apm[B_];

// ---------- constants ----------
constexpr float K_S    = 30.0f;
constexpr float K_COSM = 0.9800665778412416f;
constexpr float K_SINM = 0.19866933079506122f;
constexpr float K_TH   = -0.9800665778412416f;
constexpr float K_MM   = 0.039733866159012244f;
constexpr float K_EPS  = 0.1f;
constexpr float K_L2E  = 1.4426950408889634f;

// ---------- fast math (MUFU) ----------
__device__ __forceinline__ float exp_approx(float x) {
    float r;
    asm("ex2.approx.f32 %0, %1;" : "=f"(r) : "f"(x * K_L2E));
    return r;
}
__device__ __forceinline__ float sqrt_approx(float x) {
    float r;
    asm("sqrt.approx.f32 %0, %1;" : "=f"(r) : "f"(x));
    return r;
}

// ---------- block-wide sum ----------
__device__ __forceinline__ float block_sum_all(float v) {
    __shared__ float sh[33];
    int lane = threadIdx.x & 31, wid = threadIdx.x >> 5;
#pragma unroll
    for (int o = 16; o; o >>= 1) v += __shfl_down_sync(0xffffffffu, v, o);
    __syncthreads();
    if (lane == 0) sh[wid] = v;
    __syncthreads();
    if (threadIdx.x == 0) {
        float s = 0.f;
        int nw = (blockDim.x + 31) >> 5;
        for (int w = 0; w < nw; w++) s += sh[w];
        sh[32] = s;
    }
    __syncthreads();
    return sh[32];
}

// ---------- prep: normalize everything -> bf16 ----------
__device__ __forceinline__ void norm_row_to(const float* src, __nv_bfloat16* dst, int t) {
    const float4 v = *(const float4*)(src + t * 4);
    float tot = block_sum_all(v.x * v.x + v.y * v.y + v.z * v.z + v.w * v.w);
    float inv = 1.0f / fmaxf(sqrtf(tot), 1e-12f);
    __nv_bfloat162* o2 = (__nv_bfloat162*)(dst + t * 4);
    o2[0] = __floats2bfloat162_rn(v.x * inv, v.y * inv);
    o2[1] = __floats2bfloat162_rn(v.z * inv, v.w * inv);
}

__global__ void prep_kernel(const float* __restrict__ x, const float* __restrict__ w,
                            const float* __restrict__ wm, const float* __restrict__ wk,
                            const int* __restrict__ label) {
    int b = blockIdx.x, t = threadIdx.x;
    if (b < CPAD) {
        __nv_bfloat16* dst = g_wh + (size_t)b * D_;
        if (b >= C_) {
            __nv_bfloat162 z = __float2bfloat162_rn(0.f);
            __nv_bfloat162* o2 = (__nv_bfloat162*)(dst + t * 4);
            o2[0] = z; o2[1] = z;
            return;
        }
        norm_row_to(w + (size_t)b * D_, dst, t);
    } else if (b < CPAD + B_) {
        int r = b - CPAD;
        norm_row_to(x + (size_t)r * D_, g_xh + (size_t)r * D_, t);
    } else {
        int i = b - CPAD - B_;
        int c = label[i];
        norm_row_to(wm + (size_t)c * D_, g_wmh + (size_t)i * D_, t);
        norm_row_to(wk + (size_t)c * D_, g_wkh + (size_t)i * D_, t);
    }
}

// ---------- apm from label-matching pairs only (~2 per row): direct dots ----------
__global__ void __launch_bounds__(256)
apm_pairs_kernel(const int* __restrict__ label) {
    __shared__ int slab[B_];
    __shared__ int mlist[64];
    __shared__ int mcnt_s;
    __shared__ int wcnt[8], woff[8];
    int i = blockIdx.x, t = threadIdx.x;
    for (int j = t; j < B_; j += 256) slab[j] = label[j];
    if (t == 0) mcnt_s = 0;
    __syncthreads();
    int li = slab[i];
    for (int base = 0; base < B_; base += 256) {
        int j = base + t;
        bool m = (slab[j] == li);
        unsigned bal = __ballot_sync(0xffffffffu, m);
        int lane = t & 31, w = t >> 5;
        if (lane == 0) wcnt[w] = __popc(bal);
        __syncthreads();
        if (t == 0) {
            int off = mcnt_s;
            for (int ww = 0; ww < 8; ww++) { woff[ww] = off; off += wcnt[ww]; }
            mcnt_s = off;
        }
        __syncthreads();
        if (m) {
            int pos = woff[w] + __popc(bal & ((1u << lane) - 1u));
            if (pos < 64) mlist[pos] = j;
        }
        __syncthreads();
    }
    int cnt = mcnt_s < 64 ? mcnt_s : 64;
    float x0 = __bfloat162float(g_xh[(size_t)i * D_ + 2 * t]);
    float x1 = __bfloat162float(g_xh[(size_t)i * D_ + 2 * t + 1]);
    float ssum = 0.f, ap = 0.f;
    for (int m = 0; m < cnt; m++) {
        int j = mlist[m];
        float q0 = __bfloat162float(g_wmh[(size_t)j * D_ + 2 * t]);
        float q1 = __bfloat162float(g_wmh[(size_t)j * D_ + 2 * t + 1]);
        float k0 = __bfloat162float(g_wkh[(size_t)j * D_ + 2 * t]);
        float k1 = __bfloat162float(g_wkh[(size_t)j * D_ + 2 * t + 1]);
        float dq = block_sum_all(x0 * q0 + x1 * q1);
        float dk = block_sum_all(x0 * k0 + x1 * k1);
        float sim = dq * dk;
        ssum += sim;
        if (j == i) ap = sim;
    }
    if (t == 0) {
        float apm = ssum / (float)cnt;
        float cos_ap  = fminf(fmaxf(ap, 0.f), 1.f);
        float sin_ap  = sqrt_approx(fminf(fmaxf(1.f - cos_ap, 0.f), 1.f));
        float cos_apm = fminf(fmaxf(apm, 0.f), 1.f);
        float sin_apm = sqrt_approx(fminf(fmaxf(1.f - cos_apm, 0.f), 1.f));
        g_cos_apm[i] = cos_apm;
        g_sin_apm[i] = sin_apm;
        float pc = cos_ap * cos_apm - sin_ap * sin_apm;
        float ps = sqrt_approx(fminf(fmaxf(1.f - pc, 0.f), 1.f));
        float phi_pm = pc * K_COSM - ps * K_SINM;
        g_expneg[i] = exp_approx(1.f - phi_pm);
    }
}

// ============== mma.sync bf16 building blocks ==============
__device__ __forceinline__ void ldsm4(uint32_t& r0, uint32_t& r1, uint32_t& r2, uint32_t& r3,
                                      uint32_t addr) {
    asm volatile("ldmatrix.sync.aligned.m8n8.x4.shared.b16 {%0,%1,%2,%3},[%4];\n"
                 : "=r"(r0), "=r"(r1), "=r"(r2), "=r"(r3) : "r"(addr));
}
__device__ __forceinline__ void mma16816(float* c, const uint32_t* a, uint32_t b0, uint32_t b1) {
    asm volatile("mma.sync.aligned.m16n8k16.row.col.f32.bf16.bf16.f32 "
                 "{%0,%1,%2,%3},{%4,%5,%6,%7},{%8,%9},{%0,%1,%2,%3};\n"
                 : "+f"(c[0]), "+f"(c[1]), "+f"(c[2]), "+f"(c[3])
                 : "r"(a[0]), "r"(a[1]), "r"(a[2]), "r"(a[3]), "r"(b0), "r"(b1));
}
__device__ __forceinline__ void cpasync16(uint32_t s, const void* g) {
    asm volatile("cp.async.cg.shared.global [%0],[%1],16;\n" :: "r"(s), "l"(g));
}

#define ROWB 80
#define HALFB (128 * ROWB)          // A region: 128 rows
#define STAGEB (256 * ROWB)         // 20480 B (A:128 + B:128 rows, or A:128+Bq:64+Bk:64)
#define NSTAGE 4
#define GEMM_SMEM (NSTAGE * STAGEB) // 81920 B
#define NIT_ 16
#define WAITS(it) do {                                                     \
    if ((it) <= NIT_ - 3)      asm volatile("cp.async.wait_group 2;\n");   \
    else if ((it) == NIT_ - 2) asm volatile("cp.async.wait_group 1;\n");   \
    else                       asm volatile("cp.async.wait_group 0;\n");   \
} while (0)

// ---------------- AAM role (128x128 tile) ----------------
struct TileCtx {
    uint32_t aOff[2], bOff[4];
    uint32_t sa0, sa1, sb0, sb1;
    const __nv_bfloat16 *pa0, *pa1, *pb0, *pb1;
    int wm, wn, lane;
};

__device__ __forceinline__ void tile_init(TileCtx& T, uint32_t sbase, int tid,
                                          const __nv_bfloat16* A, const __nv_bfloat16* Bm,
                                          int bm, int bn) {
    int lane = tid & 31, warp = tid >> 5;
    T.lane = lane;
    T.wm = warp >> 1; T.wn = warp & 1;
    uint32_t sA0 = sbase, sB0 = sbase + HALFB;
    int aRow = T.wm * 32 + (lane & 7) + ((lane >> 3) & 1) * 8;
    int aCol = ((lane >> 4) & 1) * 16;
    int bRow = T.wn * 64 + (lane & 7) + ((lane >> 4) & 1) * 8;
    int bCol = ((lane >> 3) & 1) * 16;
#pragma unroll
    for (int mi = 0; mi < 2; mi++) T.aOff[mi] = sA0 + (uint32_t)((aRow + mi * 16) * ROWB + aCol);
#pragma unroll
    for (int nn = 0; nn < 4; nn++) T.bOff[nn] = sB0 + (uint32_t)((bRow + nn * 16) * ROWB + bCol);
    int c0r = tid >> 2, c0k = tid & 3;
    T.sa0 = sA0 + c0r * ROWB + c0k * 16;
    T.sa1 = sA0 + (c0r + 64) * ROWB + c0k * 16;
    T.sb0 = sB0 + c0r * ROWB + c0k * 16;
    T.sb1 = sB0 + (c0r + 64) * ROWB + c0k * 16;
    T.pa0 = A + (size_t)(bm + c0r) * D_ + c0k * 8;
    T.pa1 = A + (size_t)(bm + c0r + 64) * D_ + c0k * 8;
    T.pb0 = Bm + (size_t)(bn + c0r) * D_ + c0k * 8;
    T.pb1 = Bm + (size_t)(bn + c0r + 64) * D_ + c0k * 8;
}

__device__ __forceinline__ void tile_load(const TileCtx& T, int stage, int k0) {
    uint32_t so = (uint32_t)(stage * STAGEB);
    cpasync16(T.sa0 + so, T.pa0 + k0);
    cpasync16(T.sa1 + so, T.pa1 + k0);
    cpasync16(T.sb0 + so, T.pb0 + k0);
    cpasync16(T.sb1 + so, T.pb1 + k0);
    asm volatile("cp.async.commit_group;\n");
}

__device__ __forceinline__ void tile_compute(const TileCtx& T, int stage, float acc[2][8][4]) {
    uint32_t soff = (uint32_t)(stage * STAGEB);
#pragma unroll
    for (int ks = 0; ks < 2; ks++) {
        uint32_t a[2][4];
        ldsm4(a[0][0], a[0][1], a[0][2], a[0][3], T.aOff[0] + soff + ks * 32);
        ldsm4(a[1][0], a[1][1], a[1][2], a[1][3], T.aOff[1] + soff + ks * 32);
        uint32_t b[8][2];
#pragma unroll
        for (int nn = 0; nn < 4; nn++) {
            uint32_t r0, r1, r2, r3;
            ldsm4(r0, r1, r2, r3, T.bOff[nn] + soff + ks * 32);
            b[2 * nn][0] = r0; b[2 * nn][1] = r1;
            b[2 * nn + 1][0] = r2; b[2 * nn + 1][1] = r3;
        }
#pragma unroll
        for (int mi = 0; mi < 2; mi++)
#pragma unroll
            for (int ni = 0; ni < 8; ni++)
                mma16816(acc[mi][ni], a[mi], b[ni][0], b[ni][1]);
    }
}

// ---------------- QK role (128x64 tile, dual accumulators) ----------------
struct QkCtx {
    uint32_t aOff[2], bqOff[2], bkOff[2];
    uint32_t sa0, sa1, sq, sk;
    const __nv_bfloat16 *pa0, *pa1, *pq, *pk;
    int wm, wn, lane;
};

__device__ __forceinline__ void qk_init(QkCtx& T, uint32_t sbase, int tid,
                                        const __nv_bfloat16* A, const __nv_bfloat16* Bq,
                                        const __nv_bfloat16* Bk, int bm, int bn) {
    int lane = tid & 31, warp = tid >> 5;
    T.lane = lane;
    T.wm = warp >> 1; T.wn = warp & 1;
    uint32_t sA0 = sbase, sQ0 = sbase + HALFB, sK0 = sbase + HALFB + 64 * ROWB;
    int aRow = T.wm * 32 + (lane & 7) + ((lane >> 3) & 1) * 8;
    int aCol = ((lane >> 4) & 1) * 16;
    int bRow = T.wn * 32 + (lane & 7) + ((lane >> 4) & 1) * 8;
    int bCol = ((lane >> 3) & 1) * 16;
#pragma unroll
    for (int mi = 0; mi < 2; mi++) T.aOff[mi] = sA0 + (uint32_t)((aRow + mi * 16) * ROWB + aCol);
#pragma unroll
    for (int nn = 0; nn < 2; nn++) {
        T.bqOff[nn] = sQ0 + (uint32_t)((bRow + nn * 16) * ROWB + bCol);
        T.bkOff[nn] = sK0 + (uint32_t)((bRow + nn * 16) * ROWB + bCol);
    }
    int c0r = tid >> 2, c0k = tid & 3;   // c0r: 0..63
    T.sa0 = sA0 + c0r * ROWB + c0k * 16;
    T.sa1 = sA0 + (c0r + 64) * ROWB + c0k * 16;
    T.sq  = sQ0 + c0r * ROWB + c0k * 16;
    T.sk  = sK0 + c0r * ROWB + c0k * 16;
    T.pa0 = A  + (size_t)(bm + c0r) * D_ + c0k * 8;
    T.pa1 = A  + (size_t)(bm + c0r + 64) * D_ + c0k * 8;
    T.pq  = Bq + (size_t)(bn + c0r) * D_ + c0k * 8;
    T.pk  = Bk + (size_t)(bn + c0r) * D_ + c0k * 8;
}

__device__ __forceinline__ void qk_load(const QkCtx& T, int stage, int k0) {
    uint32_t so = (uint32_t)(stage * STAGEB);
    cpasync16(T.sa0 + so, T.pa0 + k0);
    cpasync16(T.sa1 + so, T.pa1 + k0);
    cpasync16(T.sq  + so, T.pq  + k0);
    cpasync16(T.sk  + so, T.pk  + k0);
    asm volatile("cp.async.commit_group;\n");
}

__device__ __forceinline__ void qk_compute(const QkCtx& T, int stage,
                                           float aq[2][4][4], float ak[2][4][4]) {
    uint32_t soff = (uint32_t)(stage * STAGEB);
#pragma unroll
    for (int ks = 0; ks < 2; ks++) {
        uint32_t a[2][4];
        ldsm4(a[0][0], a[0][1], a[0][2], a[0][3], T.aOff[0] + soff + ks * 32);
        ldsm4(a[1][0], a[1][1], a[1][2], a[1][3], T.aOff[1] + soff + ks * 32);
        uint32_t bq[4][2], bk[4][2];
#pragma unroll
        for (int nn = 0; nn < 2; nn++) {
            uint32_t r0, r1, r2, r3;
            ldsm4(r0, r1, r2, r3, T.bqOff[nn] + soff + ks * 32);
            bq[2 * nn][0] = r0; bq[2 * nn][1] = r1;
            bq[2 * nn + 1][0] = r2; bq[2 * nn + 1][1] = r3;
            ldsm4(r0, r1, r2, r3, T.bkOff[nn] + soff + ks * 32);
            bk[2 * nn][0] = r0; bk[2 * nn][1] = r1;
            bk[2 * nn + 1][0] = r2; bk[2 * nn + 1][1] = r3;
        }
#pragma unroll
        for (int mi = 0; mi < 2; mi++)
#pragma unroll
            for (int ni = 0; ni < 4; ni++) {
                mma16816(aq[mi][ni], a[mi], bq[ni][0], bq[ni][1]);
                mma16816(ak[mi][ni], a[mi], bk[ni][0], bk[ni][1]);
            }
    }
}

// ---------- nm term ----------
__device__ __forceinline__ float nm_term(float sim, float capm, float sapm) {
    float ca = fminf(fmaxf(sim, 0.f), 1.f);
    float sa = sqrt_approx(fminf(fmaxf(1.f - ca, 0.f), 1.f));
    float ss = sa * capm + ca * sapm;
    float cc = sqrt_approx(fminf(fmaxf(1.f - ss, 0.f), 1.f));
    return exp_approx(ss * K_COSM - cc * K_SINM);
}

// ============== mega kernel: AAM blocks + QK blocks in one launch ==============
__global__ void __launch_bounds__(256, 2)
mega_gemm(const __nv_bfloat16* __restrict__ Axh, const __nv_bfloat16* __restrict__ Bw,
          const __nv_bfloat16* __restrict__ Bwm, const __nv_bfloat16* __restrict__ Bwk,
          const int* __restrict__ label) {
    extern __shared__ __align__(16) char smem[];
    uint32_t sbase = (uint32_t)__cvta_generic_to_shared(smem);
    int tid = threadIdx.x;

    if (blockIdx.x < NAAMBLK) {
        // ---------------- AAM role ----------------
        int bx = blockIdx.x % NTC, by = blockIdx.x / NTC;
        int bm = by * 128, bn = bx * 128;
        TileCtx T;
        tile_init(T, sbase, tid, Axh, Bw, bm, bn);
        float acc[2][8][4];
#pragma unroll
        for (int mi = 0; mi < 2; mi++)
#pragma unroll
            for (int ni = 0; ni < 8; ni++)
#pragma unroll
                for (int e = 0; e < 4; e++) acc[mi][ni][e] = 0.f;

        tile_load(T, 0, 0);
        tile_load(T, 1, 32);
        tile_load(T, 2, 64);
#pragma unroll
        for (int it = 0; it < NIT_; it++) {
            WAITS(it);
            __syncthreads();
            tile_compute(T, it & 3, acc);
            if (it + 3 < NIT_) tile_load(T, (it + 3) & 3, (it + 3) * 32);
        }

        int lane = T.lane;
        int colbase = bn + T.wn * 64 + (lane & 3) * 2;
#pragma unroll
        for (int mi = 0; mi < 2; mi++) {
#pragma unroll
            for (int h = 0; h < 2; h++) {
                int row = bm + T.wm * 32 + mi * 16 + (lane >> 2) + h * 8;
                int lab = label[row];
                float se = 0.f, sc = 0.f, cy = 0.f;
#pragma unroll
                for (int ni = 0; ni < 8; ni++) {
                    int col = colbase + ni * 8;
                    float v0 = acc[mi][ni][h * 2 + 0];
                    float v1 = acc[mi][ni][h * 2 + 1];
                    if (col < C_) {
                        sc += v0;
                        se += exp_approx(K_S * (v0 - 1.f));
                        if (col == lab) cy = v0;
                    }
                    if (col + 1 < C_) {
                        sc += v1;
                        se += exp_approx(K_S * (v1 - 1.f));
                        if (col + 1 == lab) cy = v1;
                    }
                }
                se += __shfl_xor_sync(0xffffffffu, se, 1);
                se += __shfl_xor_sync(0xffffffffu, se, 2);
                sc += __shfl_xor_sync(0xffffffffu, sc, 1);
                sc += __shfl_xor_sync(0xffffffffu, sc, 2);
                cy += __shfl_xor_sync(0xffffffffu, cy, 1);
                cy += __shfl_xor_sync(0xffffffffu, cy, 2);
                if ((lane & 3) == 0) {
                    int part = bx * 2 + T.wn;
                    g_pexp[(size_t)row * NPART + part] = se;
                    g_psum[(size_t)row * NPART + part] = sc;
                    int cb = bn + T.wn * 64;
                    if (lab >= cb && lab < cb + 64) g_cy[row] = cy;
                }
            }
        }
    } else {
        // ---------------- QK role (q & k fused, nm epilogue) ----------------
        int idx = blockIdx.x - NAAMBLK;
        int cn = idx % NQCT, rm = idx / NQCT;
        int bm = rm * 128, bn = cn * 64;
        QkCtx T;
        qk_init(T, sbase, tid, Axh, Bwm, Bwk, bm, bn);
        float aq[2][4][4], ak[2][4][4];
#pragma unroll
        for (int mi = 0; mi < 2; mi++)
#pragma unroll
            for (int ni = 0; ni < 4; ni++)
#pragma unroll
                for (int e = 0; e < 4; e++) { aq[mi][ni][e] = 0.f; ak[mi][ni][e] = 0.f; }

        qk_load(T, 0, 0);
        qk_load(T, 1, 32);
        qk_load(T, 2, 64);
#pragma unroll
        for (int it = 0; it < NIT_; it++) {
            WAITS(it);
            __syncthreads();
            qk_compute(T, it & 3, aq, ak);
            if (it + 3 < NIT_) qk_load(T, (it + 3) & 3, (it + 3) * 32);
        }

        // epilogue scratch (stage smem no longer needed)
        __syncthreads();
        float* s_capm = (float*)smem;            // [64]
        float* s_sapm = s_capm + 64;             // [64]
        int*   s_lcol = (int*)(s_sapm + 64);     // [64]
        int*   s_lrow = s_lcol + 64;             // [128]
        if (tid < 64) {
            s_capm[tid] = g_cos_apm[bn + tid];
            s_sapm[tid] = g_sin_apm[bn + tid];
            s_lcol[tid] = label[bn + tid];
        } else if (tid < 192) {
            s_lrow[tid - 64] = label[bm + tid - 64];
        }
        __syncthreads();

        int lane = T.lane;
        int colloc0 = T.wn * 32 + (lane & 3) * 2;
#pragma unroll
        for (int mi = 0; mi < 2; mi++) {
#pragma unroll
            for (int h = 0; h < 2; h++) {
                int rloc = T.wm * 32 + mi * 16 + (lane >> 2) + h * 8;
                int row = bm + rloc;
                int lrow = s_lrow[rloc];
                float s = 0.f;
#pragma unroll
                for (int ni = 0; ni < 4; ni++) {
                    int cl = colloc0 + ni * 8;
                    float s0 = aq[mi][ni][h * 2 + 0] * ak[mi][ni][h * 2 + 0];
                    float s1 = aq[mi][ni][h * 2 + 1] * ak[mi][ni][h * 2 + 1];
                    if (s_lcol[cl] != lrow)     s += nm_term(s0, s_capm[cl], s_sapm[cl]);
                    if (s_lcol[cl + 1] != lrow) s += nm_term(s1, s_capm[cl + 1], s_sapm[cl + 1]);
                }
                s += __shfl_xor_sync(0xffffffffu, s, 1);
                s += __shfl_xor_sync(0xffffffffu, s, 2);
                if ((lane & 3) == 0)
                    g_nm_p[(size_t)row * NPARTQ + cn * 2 + T.wn] = s;
            }
        }
    }
}

// ---------- merged row finalize: aam rows + nm rows ----------
__global__ void finalize_rows(const int* __restrict__ label) {
    int w = threadIdx.x >> 5, lane = threadIdx.x & 31;
    if (blockIdx.x < B_ / 8) {
        int row = blockIdx.x * 8 + w;
        float se = 0.f, sc = 0.f;
        for (int j = lane; j < NPART; j += 32) {
            se += g_pexp[(size_t)row * NPART + j];
            sc += g_psum[(size_t)row * NPART + j];
        }
#pragma unroll
        for (int o = 16; o; o >>= 1) {
            se += __shfl_down_sync(0xffffffffu, se, o);
            sc += __shfl_down_sync(0xffffffffu, sc, o);
        }
        if (lane == 0) {
            float cyv = g_cy[row];
            float sine = sqrtf(fminf(fmaxf(1.f - cyv * cyv, 0.f), 1.f));
            float phi = cyv * K_COSM - sine * K_SINM;
            phi = (cyv - K_TH > 0.f) ? phi : (cyv - K_MM);
            float oy = K_S * phi, ocy = K_S * cyv;
            float sout = K_S * sc + (oy - ocy);
            se += expf(oy - K_S) - expf(ocy - K_S);
            float lse = K_S + logf(se);
            g_aam_row[row] = (1.f - K_EPS) * (oy - lse) + (K_EPS / C_) * sout - K_EPS * lse;
        }
    } else {
        int row = (blockIdx.x - B_ / 8) * 8 + w;
        float s = 0.f;
#pragma unroll
        for (int jj = 0; jj < NPARTQ / 32; jj++)
            s += g_nm_p[(size_t)row * NPARTQ + jj * 32 + lane];
#pragma unroll
        for (int o = 16; o; o >>= 1) s += __shfl_down_sync(0xffffffffu, s, o);
        if (lane == 0) g_nmp[row] = s;
    }
}

// ---------- final combine ----------
__global__ void final_combine(float* __restrict__ out) {
    float sa = 0.f, sn = 0.f, sm = 0.f;
    for (int j = threadIdx.x; j < B_; j += blockDim.x) {
        sa += g_aam_row[j];
        sn += g_expneg[j];
        sm += g_nmp[j];
    }
    sa = block_sum_all(sa);
    sn = block_sum_all(sn);
    sm = block_sum_all(sm);
    if (threadIdx.x == 0) {
        float aam_loss = -sa / (float)B_;
        float z = logf(sm) + logf(sn);
        float cc = fmaxf(z, 0.f) + log1pf(expf(-fabsf(z)));
        out[0] = aam_loss + cc;
    }
}

// ---------- launcher ----------
extern "C" void kernel_launch(void* const* d_in, const int* in_sizes, int n_in,
                              void* d_out, int out_size) {
    const float* x        = (const float*)d_in[0];
    const int*   label    = (const int*)d_in[1];
    const float* weight   = (const float*)d_in[2];
    const float* weight_m = (const float*)d_in[3];
    const float* weight_n = (const float*)d_in[4];
    float* out = (float*)d_out;

    __nv_bfloat16 *p_xh, *p_wh, *p_wmh, *p_wkh;
    cudaGetSymbolAddress((void**)&p_xh,  g_xh);
    cudaGetSymbolAddress((void**)&p_wh,  g_wh);
    cudaGetSymbolAddress((void**)&p_wmh, g_wmh);
    cudaGetSymbolAddress((void**)&p_wkh, g_wkh);

    cudaFuncSetAttribute(mega_gemm, cudaFuncAttributeMaxDynamicSharedMemorySize, GEMM_SMEM);

    prep_kernel<<<CPAD + B_ + B_, 128>>>(x, weight, weight_m, weight_n, label);
    apm_pairs_kernel<<<B_, 256>>>(label);
    mega_gemm<<<NAAMBLK + NQKBLK, 256, GEMM_SMEM>>>(p_xh, p_wh, p_wmh, p_wkh, label);
    finalize_rows<<<2 * (B_ / 8), 256>>>(label);
    final_combine<<<1, 256>>>(out);
}

// round 8
// speedup vs baseline: 7.2475x; 1.0738x over previous
#include <cuda_runtime.h>
#include <cuda_bf16.h>
#include <math.h>
#include <stdint.h>

#define B_ 2048
#define D_ 512
#define C_ 10000
#define CPAD 10112          // 79 * 128
#define NTC 79              // AAM col tiles of 128
#define NQCT 32             // QK col tiles of 64
#define NAAMBLK (NTC * (B_ / 128))        // 1264
#define NQKBLK  (NQCT * (B_ / 128))       // 512

// ---------- scratch (device globals: alloc-free, capture-safe) ----------
__device__ __nv_bfloat16 g_xh[B_ * D_];
__device__ __nv_bfloat16 g_wh[(size_t)CPAD * D_];
__device__ __nv_bfloat16 g_wmh[B_ * D_];
__device__ __nv_bfloat16 g_wkh[B_ * D_];
__device__ float g_rexp[B_];     // atomic: sum exp(S(c-1)) per row
__device__ float g_rsum[B_];     // atomic: sum c per row
__device__ float g_nmp[B_];      // atomic: sum exp(phi_nm) per row
__device__ float g_cy[B_];
__device__ float g_expneg[B_];
__device__ float g_cos_apm[B_];
__device__ float g_sin_apm[B_];

// ---------- constants ----------
constexpr float K_S    = 30.0f;
constexpr float K_COSM = 0.9800665778412416f;
constexpr float K_SINM = 0.19866933079506122f;
constexpr float K_TH   = -0.9800665778412416f;
constexpr float K_MM   = 0.039733866159012244f;
constexpr float K_EPS  = 0.1f;
constexpr float K_L2E  = 1.4426950408889634f;

// ---------- fast math (MUFU) ----------
__device__ __forceinline__ float exp_approx(float x) {
    float r;
    asm("ex2.approx.f32 %0, %1;" : "=f"(r) : "f"(x * K_L2E));
    return r;
}
__device__ __forceinline__ float sqrt_approx(float x) {
    float r;
    asm("sqrt.approx.f32 %0, %1;" : "=f"(r) : "f"(x));
    return r;
}

// ---------- block-wide sum ----------
__device__ __forceinline__ float block_sum_all(float v) {
    __shared__ float sh[33];
    int lane = threadIdx.x & 31, wid = threadIdx.x >> 5;
#pragma unroll
    for (int o = 16; o; o >>= 1) v += __shfl_down_sync(0xffffffffu, v, o);
    __syncthreads();
    if (lane == 0) sh[wid] = v;
    __syncthreads();
    if (threadIdx.x == 0) {
        float s = 0.f;
        int nw = (blockDim.x + 31) >> 5;
        for (int w = 0; w < nw; w++) s += sh[w];
        sh[32] = s;
    }
    __syncthreads();
    return sh[32];
}

// ---------- prep: normalize all + zero accumulators ----------
__device__ __forceinline__ void norm_row_to(const float* src, __nv_bfloat16* dst, int t) {
    const float4 v = *(const float4*)(src + t * 4);
    float tot = block_sum_all(v.x * v.x + v.y * v.y + v.z * v.z + v.w * v.w);
    float inv = 1.0f / fmaxf(sqrtf(tot), 1e-12f);
    __nv_bfloat162* o2 = (__nv_bfloat162*)(dst + t * 4);
    o2[0] = __floats2bfloat162_rn(v.x * inv, v.y * inv);
    o2[1] = __floats2bfloat162_rn(v.z * inv, v.w * inv);
}

#define PREP_ZBASE (CPAD + B_ + B_)
__global__ void prep_kernel(const float* __restrict__ x, const float* __restrict__ w,
                            const float* __restrict__ wm, const float* __restrict__ wk,
                            const int* __restrict__ label) {
    int b = blockIdx.x, t = threadIdx.x;
    if (b < CPAD) {
        __nv_bfloat16* dst = g_wh + (size_t)b * D_;
        if (b >= C_) {
            __nv_bfloat162 z = __float2bfloat162_rn(0.f);
            __nv_bfloat162* o2 = (__nv_bfloat162*)(dst + t * 4);
            o2[0] = z; o2[1] = z;
            return;
        }
        norm_row_to(w + (size_t)b * D_, dst, t);
    } else if (b < CPAD + B_) {
        int r = b - CPAD;
        norm_row_to(x + (size_t)r * D_, g_xh + (size_t)r * D_, t);
    } else if (b < PREP_ZBASE) {
        int i = b - CPAD - B_;
        int c = label[i];
        norm_row_to(wm + (size_t)c * D_, g_wmh + (size_t)i * D_, t);
        norm_row_to(wk + (size_t)c * D_, g_wkh + (size_t)i * D_, t);
    } else {
        int z = b - PREP_ZBASE;     // 48 blocks x 128 threads
        int idx = (z & 15) * 128 + t;
        if (z < 16)      g_rexp[idx] = 0.f;
        else if (z < 32) g_rsum[idx] = 0.f;
        else             g_nmp[idx]  = 0.f;
    }
}

// ---------- apm: warp per row, ~2 matched pairs, direct dots ----------
__global__ void __launch_bounds__(256)
apm_pairs_kernel(const int* __restrict__ label) {
    __shared__ int slab[B_];
    __shared__ int mlist[8][32];
    int t = threadIdx.x, w = t >> 5, lane = t & 31;
    for (int j = t; j < B_; j += 256) slab[j] = label[j];
    __syncthreads();
    int i = blockIdx.x * 8 + w;
    int li = slab[i];
    int cnt = 0;
    for (int base = 0; base < B_; base += 32) {
        int j = base + lane;
        bool m = (slab[j] == li);
        unsigned bal = __ballot_sync(0xffffffffu, m);
        if (m) {
            int pos = cnt + __popc(bal & ((1u << lane) - 1u));
            if (pos < 32) mlist[w][pos] = j;
        }
        cnt += __popc(bal);
    }
    __syncwarp();
    if (cnt > 32) cnt = 32;
    // lane handles dims [lane*16, lane*16+16): 2 float4 (= 16 bf16)
    float xv[16];
    {
        const float4* xp = (const float4*)(g_xh + (size_t)i * D_ + lane * 16);
        float4 a = xp[0], bq = xp[1];
        const __nv_bfloat162* pa = (const __nv_bfloat162*)&a;
        const __nv_bfloat162* pb = (const __nv_bfloat162*)&bq;
#pragma unroll
        for (int e = 0; e < 4; e++) {
            float2 f0 = __bfloat1622float2(pa[e]);
            float2 f1 = __bfloat1622float2(pb[e]);
            xv[2 * e] = f0.x; xv[2 * e + 1] = f0.y;
            xv[8 + 2 * e] = f1.x; xv[8 + 2 * e + 1] = f1.y;
        }
    }
    float ssum = 0.f, ap = 0.f;
    for (int m = 0; m < cnt; m++) {
        int j = mlist[w][m];
        float dq = 0.f, dk = 0.f;
        const float4* qp = (const float4*)(g_wmh + (size_t)j * D_ + lane * 16);
        const float4* kp = (const float4*)(g_wkh + (size_t)j * D_ + lane * 16);
        float4 q0 = qp[0], q1 = qp[1], k0 = kp[0], k1 = kp[1];
        const __nv_bfloat162* pq0 = (const __nv_bfloat162*)&q0;
        const __nv_bfloat162* pq1 = (const __nv_bfloat162*)&q1;
        const __nv_bfloat162* pk0 = (const __nv_bfloat162*)&k0;
        const __nv_bfloat162* pk1 = (const __nv_bfloat162*)&k1;
#pragma unroll
        for (int e = 0; e < 4; e++) {
            float2 fq0 = __bfloat1622float2(pq0[e]);
            float2 fq1 = __bfloat1622float2(pq1[e]);
            float2 fk0 = __bfloat1622float2(pk0[e]);
            float2 fk1 = __bfloat1622float2(pk1[e]);
            dq += xv[2 * e] * fq0.x + xv[2 * e + 1] * fq0.y
                + xv[8 + 2 * e] * fq1.x + xv[8 + 2 * e + 1] * fq1.y;
            dk += xv[2 * e] * fk0.x + xv[2 * e + 1] * fk0.y
                + xv[8 + 2 * e] * fk1.x + xv[8 + 2 * e + 1] * fk1.y;
        }
#pragma unroll
        for (int o = 16; o; o >>= 1) {
            dq += __shfl_xor_sync(0xffffffffu, dq, o);
            dk += __shfl_xor_sync(0xffffffffu, dk, o);
        }
        float sim = dq * dk;
        ssum += sim;
        if (j == i) ap = sim;
    }
    if (lane == 0) {
        float apm = ssum / (float)cnt;
        float cos_ap  = fminf(fmaxf(ap, 0.f), 1.f);
        float sin_ap  = sqrt_approx(fminf(fmaxf(1.f - cos_ap, 0.f), 1.f));
        float cos_apm = fminf(fmaxf(apm, 0.f), 1.f);
        float sin_apm = sqrt_approx(fminf(fmaxf(1.f - cos_apm, 0.f), 1.f));
        g_cos_apm[i] = cos_apm;
        g_sin_apm[i] = sin_apm;
        float pc = cos_ap * cos_apm - sin_ap * sin_apm;
        float ps = sqrt_approx(fminf(fmaxf(1.f - pc, 0.f), 1.f));
        float phi_pm = pc * K_COSM - ps * K_SINM;
        g_expneg[i] = exp_approx(1.f - phi_pm);
    }
}

// ============== mma.sync bf16 building blocks ==============
__device__ __forceinline__ void ldsm4(uint32_t& r0, uint32_t& r1, uint32_t& r2, uint32_t& r3,
                                      uint32_t addr) {
    asm volatile("ldmatrix.sync.aligned.m8n8.x4.shared.b16 {%0,%1,%2,%3},[%4];\n"
                 : "=r"(r0), "=r"(r1), "=r"(r2), "=r"(r3) : "r"(addr));
}
__device__ __forceinline__ void mma16816(float* c, const uint32_t* a, uint32_t b0, uint32_t b1) {
    asm volatile("mma.sync.aligned.m16n8k16.row.col.f32.bf16.bf16.f32 "
                 "{%0,%1,%2,%3},{%4,%5,%6,%7},{%8,%9},{%0,%1,%2,%3};\n"
                 : "+f"(c[0]), "+f"(c[1]), "+f"(c[2]), "+f"(c[3])
                 : "r"(a[0]), "r"(a[1]), "r"(a[2]), "r"(a[3]), "r"(b0), "r"(b1));
}
__device__ __forceinline__ void cpasync16(uint32_t s, const void* g) {
    asm volatile("cp.async.cg.shared.global [%0],[%1],16;\n" :: "r"(s), "l"(g));
}

#define ROWB 80
#define HALFB (128 * ROWB)
#define STAGEB (256 * ROWB)         // 20480 B
#define NSTAGE 4
#define GEMM_SMEM (NSTAGE * STAGEB) // 81920 B
#define NIT_ 16
#define WAITS(it) do {                                                     \
    if ((it) <= NIT_ - 3)      asm volatile("cp.async.wait_group 2;\n");   \
    else if ((it) == NIT_ - 2) asm volatile("cp.async.wait_group 1;\n");   \
    else                       asm volatile("cp.async.wait_group 0;\n");   \
} while (0)

// ---------------- AAM role (128x128 tile) ----------------
struct TileCtx {
    uint32_t aOff[2], bOff[4];
    uint32_t sa0, sa1, sb0, sb1;
    const __nv_bfloat16 *pa0, *pa1, *pb0, *pb1;
    int wm, wn, lane;
};

__device__ __forceinline__ void tile_init(TileCtx& T, uint32_t sbase, int tid,
                                          const __nv_bfloat16* A, const __nv_bfloat16* Bm,
                                          int bm, int bn) {
    int lane = tid & 31, warp = tid >> 5;
    T.lane = lane;
    T.wm = warp >> 1; T.wn = warp & 1;
    uint32_t sA0 = sbase, sB0 = sbase + HALFB;
    int aRow = T.wm * 32 + (lane & 7) + ((lane >> 3) & 1) * 8;
    int aCol = ((lane >> 4) & 1) * 16;
    int bRow = T.wn * 64 + (lane & 7) + ((lane >> 4) & 1) * 8;
    int bCol = ((lane >> 3) & 1) * 16;
#pragma unroll
    for (int mi = 0; mi < 2; mi++) T.aOff[mi] = sA0 + (uint32_t)((aRow + mi * 16) * ROWB + aCol);
#pragma unroll
    for (int nn = 0; nn < 4; nn++) T.bOff[nn] = sB0 + (uint32_t)((bRow + nn * 16) * ROWB + bCol);
    int c0r = tid >> 2, c0k = tid & 3;
    T.sa0 = sA0 + c0r * ROWB + c0k * 16;
    T.sa1 = sA0 + (c0r + 64) * ROWB + c0k * 16;
    T.sb0 = sB0 + c0r * ROWB + c0k * 16;
    T.sb1 = sB0 + (c0r + 64) * ROWB + c0k * 16;
    T.pa0 = A + (size_t)(bm + c0r) * D_ + c0k * 8;
    T.pa1 = A + (size_t)(bm + c0r + 64) * D_ + c0k * 8;
    T.pb0 = Bm + (size_t)(bn + c0r) * D_ + c0k * 8;
    T.pb1 = Bm + (size_t)(bn + c0r + 64) * D_ + c0k * 8;
}

__device__ __forceinline__ void tile_load(const TileCtx& T, int stage, int k0) {
    uint32_t so = (uint32_t)(stage * STAGEB);
    cpasync16(T.sa0 + so, T.pa0 + k0);
    cpasync16(T.sa1 + so, T.pa1 + k0);
    cpasync16(T.sb0 + so, T.pb0 + k0);
    cpasync16(T.sb1 + so, T.pb1 + k0);
    asm volatile("cp.async.commit_group;\n");
}

__device__ __forceinline__ void tile_compute(const TileCtx& T, int stage, float acc[2][8][4]) {
    uint32_t soff = (uint32_t)(stage * STAGEB);
#pragma unroll
    for (int ks = 0; ks < 2; ks++) {
        uint32_t a[2][4];
        ldsm4(a[0][0], a[0][1], a[0][2], a[0][3], T.aOff[0] + soff + ks * 32);
        ldsm4(a[1][0], a[1][1], a[1][2], a[1][3], T.aOff[1] + soff + ks * 32);
        uint32_t b[8][2];
#pragma unroll
        for (int nn = 0; nn < 4; nn++) {
            uint32_t r0, r1, r2, r3;
            ldsm4(r0, r1, r2, r3, T.bOff[nn] + soff + ks * 32);
            b[2 * nn][0] = r0; b[2 * nn][1] = r1;
            b[2 * nn + 1][0] = r2; b[2 * nn + 1][1] = r3;
        }
#pragma unroll
        for (int mi = 0; mi < 2; mi++)
#pragma unroll
            for (int ni = 0; ni < 8; ni++)
                mma16816(acc[mi][ni], a[mi], b[ni][0], b[ni][1]);
    }
}

// ---------------- QK role (128x64 tile, dual accumulators) ----------------
struct QkCtx {
    uint32_t aOff[2], bqOff[2], bkOff[2];
    uint32_t sa0, sa1, sq, sk;
    const __nv_bfloat16 *pa0, *pa1, *pq, *pk;
    int wm, wn, lane;
};

__device__ __forceinline__ void qk_init(QkCtx& T, uint32_t sbase, int tid,
                                        const __nv_bfloat16* A, const __nv_bfloat16* Bq,
                                        const __nv_bfloat16* Bk, int bm, int bn) {
    int lane = tid & 31, warp = tid >> 5;
    T.lane = lane;
    T.wm = warp >> 1; T.wn = warp & 1;
    uint32_t sA0 = sbase, sQ0 = sbase + HALFB, sK0 = sbase + HALFB + 64 * ROWB;
    int aRow = T.wm * 32 + (lane & 7) + ((lane >> 3) & 1) * 8;
    int aCol = ((lane >> 4) & 1) * 16;
    int bRow = T.wn * 32 + (lane & 7) + ((lane >> 4) & 1) * 8;
    int bCol = ((lane >> 3) & 1) * 16;
#pragma unroll
    for (int mi = 0; mi < 2; mi++) T.aOff[mi] = sA0 + (uint32_t)((aRow + mi * 16) * ROWB + aCol);
#pragma unroll
    for (int nn = 0; nn < 2; nn++) {
        T.bqOff[nn] = sQ0 + (uint32_t)((bRow + nn * 16) * ROWB + bCol);
        T.bkOff[nn] = sK0 + (uint32_t)((bRow + nn * 16) * ROWB + bCol);
    }
    int c0r = tid >> 2, c0k = tid & 3;
    T.sa0 = sA0 + c0r * ROWB + c0k * 16;
    T.sa1 = sA0 + (c0r + 64) * ROWB + c0k * 16;
    T.sq  = sQ0 + c0r * ROWB + c0k * 16;
    T.sk  = sK0 + c0r * ROWB + c0k * 16;
    T.pa0 = A  + (size_t)(bm + c0r) * D_ + c0k * 8;
    T.pa1 = A  + (size_t)(bm + c0r + 64) * D_ + c0k * 8;
    T.pq  = Bq + (size_t)(bn + c0r) * D_ + c0k * 8;
    T.pk  = Bk + (size_t)(bn + c0r) * D_ + c0k * 8;
}

__device__ __forceinline__ void qk_load(const QkCtx& T, int stage, int k0) {
    uint32_t so = (uint32_t)(stage * STAGEB);
    cpasync16(T.sa0 + so, T.pa0 + k0);
    cpasync16(T.sa1 + so, T.pa1 + k0);
    cpasync16(T.sq  + so, T.pq  + k0);
    cpasync16(T.sk  + so, T.pk  + k0);
    asm volatile("cp.async.commit_group;\n");
}

__device__ __forceinline__ void qk_compute(const QkCtx& T, int stage,
                                           float aq[2][4][4], float ak[2][4][4]) {
    uint32_t soff = (uint32_t)(stage * STAGEB);
#pragma unroll
    for (int ks = 0; ks < 2; ks++) {
        uint32_t a[2][4];
        ldsm4(a[0][0], a[0][1], a[0][2], a[0][3], T.aOff[0] + soff + ks * 32);
        ldsm4(a[1][0], a[1][1], a[1][2], a[1][3], T.aOff[1] + soff + ks * 32);
        uint32_t bq[4][2], bk[4][2];
#pragma unroll
        for (int nn = 0; nn < 2; nn++) {
            uint32_t r0, r1, r2, r3;
            ldsm4(r0, r1, r2, r3, T.bqOff[nn] + soff + ks * 32);
            bq[2 * nn][0] = r0; bq[2 * nn][1] = r1;
            bq[2 * nn + 1][0] = r2; bq[2 * nn + 1][1] = r3;
            ldsm4(r0, r1, r2, r3, T.bkOff[nn] + soff + ks * 32);
            bk[2 * nn][0] = r0; bk[2 * nn][1] = r1;
            bk[2 * nn + 1][0] = r2; bk[2 * nn + 1][1] = r3;
        }
#pragma unroll
        for (int mi = 0; mi < 2; mi++)
#pragma unroll
            for (int ni = 0; ni < 4; ni++) {
                mma16816(aq[mi][ni], a[mi], bq[ni][0], bq[ni][1]);
                mma16816(ak[mi][ni], a[mi], bk[ni][0], bk[ni][1]);
            }
    }
}

// ---------- nm term ----------
__device__ __forceinline__ float nm_term(float sim, float capm, float sapm) {
    float ca = fminf(fmaxf(sim, 0.f), 1.f);
    float sa = sqrt_approx(fminf(fmaxf(1.f - ca, 0.f), 1.f));
    float ss = sa * capm + ca * sapm;
    float cc = sqrt_approx(fminf(fmaxf(1.f - ss, 0.f), 1.f));
    return exp_approx(ss * K_COSM - cc * K_SINM);
}

// ============== mega kernel: AAM blocks + QK blocks, atomic row accumulation ==============
__global__ void __launch_bounds__(256, 2)
mega_gemm(const __nv_bfloat16* __restrict__ Axh, const __nv_bfloat16* __restrict__ Bw,
          const __nv_bfloat16* __restrict__ Bwm, const __nv_bfloat16* __restrict__ Bwk,
          const int* __restrict__ label) {
    extern __shared__ __align__(16) char smem[];
    uint32_t sbase = (uint32_t)__cvta_generic_to_shared(smem);
    int tid = threadIdx.x;

    if (blockIdx.x < NAAMBLK) {
        int bx = blockIdx.x % NTC, by = blockIdx.x / NTC;
        int bm = by * 128, bn = bx * 128;
        TileCtx T;
        tile_init(T, sbase, tid, Axh, Bw, bm, bn);
        float acc[2][8][4];
#pragma unroll
        for (int mi = 0; mi < 2; mi++)
#pragma unroll
            for (int ni = 0; ni < 8; ni++)
#pragma unroll
                for (int e = 0; e < 4; e++) acc[mi][ni][e] = 0.f;

        tile_load(T, 0, 0);
        tile_load(T, 1, 32);
        tile_load(T, 2, 64);
#pragma unroll
        for (int it = 0; it < NIT_; it++) {
            WAITS(it);
            __syncthreads();
            tile_compute(T, it & 3, acc);
            if (it + 3 < NIT_) tile_load(T, (it + 3) & 3, (it + 3) * 32);
        }

        int lane = T.lane;
        int colbase = bn + T.wn * 64 + (lane & 3) * 2;
#pragma unroll
        for (int mi = 0; mi < 2; mi++) {
#pragma unroll
            for (int h = 0; h < 2; h++) {
                int row = bm + T.wm * 32 + mi * 16 + (lane >> 2) + h * 8;
                int lab = label[row];
                float se = 0.f, sc = 0.f, cy = 0.f;
#pragma unroll
                for (int ni = 0; ni < 8; ni++) {
                    int col = colbase + ni * 8;
                    float v0 = acc[mi][ni][h * 2 + 0];
                    float v1 = acc[mi][ni][h * 2 + 1];
                    if (col < C_) {
                        sc += v0;
                        se += exp_approx(K_S * (v0 - 1.f));
                        if (col == lab) cy = v0;
                    }
                    if (col + 1 < C_) {
                        sc += v1;
                        se += exp_approx(K_S * (v1 - 1.f));
                        if (col + 1 == lab) cy = v1;
                    }
                }
                se += __shfl_xor_sync(0xffffffffu, se, 1);
                se += __shfl_xor_sync(0xffffffffu, se, 2);
                sc += __shfl_xor_sync(0xffffffffu, sc, 1);
                sc += __shfl_xor_sync(0xffffffffu, sc, 2);
                cy += __shfl_xor_sync(0xffffffffu, cy, 1);
                cy += __shfl_xor_sync(0xffffffffu, cy, 2);
                if ((lane & 3) == 0) {
                    atomicAdd(&g_rexp[row], se);
                    atomicAdd(&g_rsum[row], sc);
                    int cb = bn + T.wn * 64;
                    if (lab >= cb && lab < cb + 64) g_cy[row] = cy;
                }
            }
        }
    } else {
        int idx = blockIdx.x - NAAMBLK;
        int cn = idx % NQCT, rm = idx / NQCT;
        int bm = rm * 128, bn = cn * 64;
        QkCtx T;
        qk_init(T, sbase, tid, Axh, Bwm, Bwk, bm, bn);
        float aq[2][4][4], ak[2][4][4];
#pragma unroll
        for (int mi = 0; mi < 2; mi++)
#pragma unroll
            for (int ni = 0; ni < 4; ni++)
#pragma unroll
                for (int e = 0; e < 4; e++) { aq[mi][ni][e] = 0.f; ak[mi][ni][e] = 0.f; }

        qk_load(T, 0, 0);
        qk_load(T, 1, 32);
        qk_load(T, 2, 64);
#pragma unroll
        for (int it = 0; it < NIT_; it++) {
            WAITS(it);
            __syncthreads();
            qk_compute(T, it & 3, aq, ak);
            if (it + 3 < NIT_) qk_load(T, (it + 3) & 3, (it + 3) * 32);
        }

        __syncthreads();
        float* s_capm = (float*)smem;
        float* s_sapm = s_capm + 64;
        int*   s_lcol = (int*)(s_sapm + 64);
        int*   s_lrow = s_lcol + 64;
        if (tid < 64) {
            s_capm[tid] = g_cos_apm[bn + tid];
            s_sapm[tid] = g_sin_apm[bn + tid];
            s_lcol[tid] = label[bn + tid];
        } else if (tid < 192) {
            s_lrow[tid - 64] = label[bm + tid - 64];
        }
        __syncthreads();

        int lane = T.lane;
        int colloc0 = T.wn * 32 + (lane & 3) * 2;
#pragma unroll
        for (int mi = 0; mi < 2; mi++) {
#pragma unroll
            for (int h = 0; h < 2; h++) {
                int rloc = T.wm * 32 + mi * 16 + (lane >> 2) + h * 8;
                int row = bm + rloc;
                int lrow = s_lrow[rloc];
                float s = 0.f;
#pragma unroll
                for (int ni = 0; ni < 4; ni++) {
                    int cl = colloc0 + ni * 8;
                    float s0 = aq[mi][ni][h * 2 + 0] * ak[mi][ni][h * 2 + 0];
                    float s1 = aq[mi][ni][h * 2 + 1] * ak[mi][ni][h * 2 + 1];
                    if (s_lcol[cl] != lrow)     s += nm_term(s0, s_capm[cl], s_sapm[cl]);
                    if (s_lcol[cl + 1] != lrow) s += nm_term(s1, s_capm[cl + 1], s_sapm[cl + 1]);
                }
                s += __shfl_xor_sync(0xffffffffu, s, 1);
                s += __shfl_xor_sync(0xffffffffu, s, 2);
                if ((lane & 3) == 0)
                    atomicAdd(&g_nmp[row], s);
            }
        }
    }
}

// ---------- final combine: per-row AAM math + global reductions ----------
__global__ void final_combine(const int* __restrict__ label, float* __restrict__ out) {
    float sa = 0.f, sn = 0.f, sm = 0.f;
    for (int j = threadIdx.x; j < B_; j += blockDim.x) {
        float se = g_rexp[j];
        float sc = g_rsum[j];
        float cyv = g_cy[j];
        float sine = sqrtf(fminf(fmaxf(1.f - cyv * cyv, 0.f), 1.f));
        float phi = cyv * K_COSM - sine * K_SINM;
        phi = (cyv - K_TH > 0.f) ? phi : (cyv - K_MM);
        float oy = K_S * phi, ocy = K_S * cyv;
        float sout = K_S * sc + (oy - ocy);
        se += expf(oy - K_S) - expf(ocy - K_S);
        float lse = K_S + logf(se);
        sa += (1.f - K_EPS) * (oy - lse) + (K_EPS / C_) * sout - K_EPS * lse;
        sn += g_expneg[j];
        sm += g_nmp[j];
    }
    sa = block_sum_all(sa);
    sn = block_sum_all(sn);
    sm = block_sum_all(sm);
    if (threadIdx.x == 0) {
        float aam_loss = -sa / (float)B_;
        float z = logf(sm) + logf(sn);
        float cc = fmaxf(z, 0.f) + log1pf(expf(-fabsf(z)));
        out[0] = aam_loss + cc;
    }
}

// ---------- launcher ----------
extern "C" void kernel_launch(void* const* d_in, const int* in_sizes, int n_in,
                              void* d_out, int out_size) {
    const float* x        = (const float*)d_in[0];
    const int*   label    = (const int*)d_in[1];
    const float* weight   = (const float*)d_in[2];
    const float* weight_m = (const float*)d_in[3];
    const float* weight_n = (const float*)d_in[4];
    float* out = (float*)d_out;

    __nv_bfloat16 *p_xh, *p_wh, *p_wmh, *p_wkh;
    cudaGetSymbolAddress((void**)&p_xh,  g_xh);
    cudaGetSymbolAddress((void**)&p_wh,  g_wh);
    cudaGetSymbolAddress((void**)&p_wmh, g_wmh);
    cudaGetSymbolAddress((void**)&p_wkh, g_wkh);

    cudaFuncSetAttribute(mega_gemm, cudaFuncAttributeMaxDynamicSharedMemorySize, GEMM_SMEM);

    prep_kernel<<<PREP_ZBASE + 48, 128>>>(x, weight, weight_m, weight_n, label);
    apm_pairs_kernel<<<B_ / 8, 256>>>(label);
    mega_gemm<<<NAAMBLK + NQKBLK, 256, GEMM_SMEM>>>(p_xh, p_wh, p_wmh, p_wkh, label);
    final_combine<<<1, 256>>>(label, out);
}

// round 9
// speedup vs baseline: 7.3556x; 1.0149x over previous
#include <cuda_runtime.h>
#include <cuda_bf16.h>
#include <math.h>
#include <stdint.h>

#define B_ 2048
#define D_ 512
#define C_ 10000
#define CPAD 10112          // 79 * 128
#define NTC 79              // AAM col tiles of 128
#define NQCT 32             // QK col tiles of 64
#define NAAMBLK (NTC * (B_ / 128))        // 1264
#define NQKBLK  (NQCT * (B_ / 128))       // 512
#define NFINAL 8

// ---------- scratch (device globals: alloc-free, capture-safe) ----------
__device__ __nv_bfloat16 g_xh[B_ * D_];
__device__ __nv_bfloat16 g_wh[(size_t)CPAD * D_];
__device__ __nv_bfloat16 g_wmh[B_ * D_];
__device__ __nv_bfloat16 g_wkh[B_ * D_];
__device__ float g_rexp[B_];     // atomic: sum exp(S(c-1)) per row
__device__ float g_rsum[B_];     // atomic: sum c per row
__device__ float g_nmp[B_];      // atomic: sum exp(phi_nm) per row
__device__ float g_cy[B_];
__device__ float g_expneg[B_];
__device__ float g_cos_apm[B_];
__device__ float g_sin_apm[B_];
__device__ float g_acc[3];       // atomic: sa, sn, sm
__device__ unsigned g_ticket;

// ---------- constants ----------
constexpr float K_S    = 30.0f;
constexpr float K_COSM = 0.9800665778412416f;
constexpr float K_SINM = 0.19866933079506122f;
constexpr float K_TH   = -0.9800665778412416f;
constexpr float K_MM   = 0.039733866159012244f;
constexpr float K_EPS  = 0.1f;
constexpr float K_L2E  = 1.4426950408889634f;
constexpr float K_LN2  = 0.6931471805599453f;

// ---------- fast math (MUFU) ----------
__device__ __forceinline__ float exp_approx(float x) {
    float r;
    asm("ex2.approx.f32 %0, %1;" : "=f"(r) : "f"(x * K_L2E));
    return r;
}
__device__ __forceinline__ float log_approx(float x) {
    float r;
    asm("lg2.approx.f32 %0, %1;" : "=f"(r) : "f"(x));
    return r * K_LN2;
}
__device__ __forceinline__ float sqrt_approx(float x) {
    float r;
    asm("sqrt.approx.f32 %0, %1;" : "=f"(r) : "f"(x));
    return r;
}

// ---------- block-wide sum ----------
__device__ __forceinline__ float block_sum_all(float v) {
    __shared__ float sh[33];
    int lane = threadIdx.x & 31, wid = threadIdx.x >> 5;
#pragma unroll
    for (int o = 16; o; o >>= 1) v += __shfl_down_sync(0xffffffffu, v, o);
    __syncthreads();
    if (lane == 0) sh[wid] = v;
    __syncthreads();
    if (threadIdx.x == 0) {
        float s = 0.f;
        int nw = (blockDim.x + 31) >> 5;
        for (int w = 0; w < nw; w++) s += sh[w];
        sh[32] = s;
    }
    __syncthreads();
    return sh[32];
}

// ---------- prep: normalize all + zero accumulators/controls ----------
__device__ __forceinline__ void norm_row_to(const float* src, __nv_bfloat16* dst, int t) {
    const float4 v = *(const float4*)(src + t * 4);
    float tot = block_sum_all(v.x * v.x + v.y * v.y + v.z * v.z + v.w * v.w);
    float inv = 1.0f / fmaxf(sqrtf(tot), 1e-12f);
    __nv_bfloat162* o2 = (__nv_bfloat162*)(dst + t * 4);
    o2[0] = __floats2bfloat162_rn(v.x * inv, v.y * inv);
    o2[1] = __floats2bfloat162_rn(v.z * inv, v.w * inv);
}

#define PREP_ZBASE (CPAD + B_ + B_)
__global__ void prep_kernel(const float* __restrict__ x, const float* __restrict__ w,
                            const float* __restrict__ wm, const float* __restrict__ wk,
                            const int* __restrict__ label) {
    int b = blockIdx.x, t = threadIdx.x;
    if (b < CPAD) {
        __nv_bfloat16* dst = g_wh + (size_t)b * D_;
        if (b >= C_) {
            __nv_bfloat162 z = __float2bfloat162_rn(0.f);
            __nv_bfloat162* o2 = (__nv_bfloat162*)(dst + t * 4);
            o2[0] = z; o2[1] = z;
            return;
        }
        norm_row_to(w + (size_t)b * D_, dst, t);
    } else if (b < CPAD + B_) {
        int r = b - CPAD;
        norm_row_to(x + (size_t)r * D_, g_xh + (size_t)r * D_, t);
    } else if (b < PREP_ZBASE) {
        int i = b - CPAD - B_;
        int c = label[i];
        norm_row_to(wm + (size_t)c * D_, g_wmh + (size_t)i * D_, t);
        norm_row_to(wk + (size_t)c * D_, g_wkh + (size_t)i * D_, t);
    } else {
        int z = b - PREP_ZBASE;
        if (z < 48) {
            int idx = (z & 15) * 128 + t;
            if (z < 16)      g_rexp[idx] = 0.f;
            else if (z < 32) g_rsum[idx] = 0.f;
            else             g_nmp[idx]  = 0.f;
        } else {
            if (t < 3) g_acc[t] = 0.f;
            if (t == 3) g_ticket = 0u;
        }
    }
}

// ---------- apm: warp per row, ~2 matched pairs, direct dots ----------
__global__ void __launch_bounds__(256)
apm_pairs_kernel(const int* __restrict__ label) {
    __shared__ int slab[B_];
    __shared__ int mlist[8][32];
    int t = threadIdx.x, w = t >> 5, lane = t & 31;
    for (int j = t; j < B_; j += 256) slab[j] = label[j];
    __syncthreads();
    int i = blockIdx.x * 8 + w;
    int li = slab[i];
    int cnt = 0;
    for (int base = 0; base < B_; base += 32) {
        int j = base + lane;
        bool m = (slab[j] == li);
        unsigned bal = __ballot_sync(0xffffffffu, m);
        if (m) {
            int pos = cnt + __popc(bal & ((1u << lane) - 1u));
            if (pos < 32) mlist[w][pos] = j;
        }
        cnt += __popc(bal);
    }
    __syncwarp();
    if (cnt > 32) cnt = 32;
    float xv[16];
    {
        const float4* xp = (const float4*)(g_xh + (size_t)i * D_ + lane * 16);
        float4 a = xp[0], bq = xp[1];
        const __nv_bfloat162* pa = (const __nv_bfloat162*)&a;
        const __nv_bfloat162* pb = (const __nv_bfloat162*)&bq;
#pragma unroll
        for (int e = 0; e < 4; e++) {
            float2 f0 = __bfloat1622float2(pa[e]);
            float2 f1 = __bfloat1622float2(pb[e]);
            xv[2 * e] = f0.x; xv[2 * e + 1] = f0.y;
            xv[8 + 2 * e] = f1.x; xv[8 + 2 * e + 1] = f1.y;
        }
    }
    float ssum = 0.f, ap = 0.f;
    for (int m = 0; m < cnt; m++) {
        int j = mlist[w][m];
        float dq = 0.f, dk = 0.f;
        const float4* qp = (const float4*)(g_wmh + (size_t)j * D_ + lane * 16);
        const float4* kp = (const float4*)(g_wkh + (size_t)j * D_ + lane * 16);
        float4 q0 = qp[0], q1 = qp[1], k0 = kp[0], k1 = kp[1];
        const __nv_bfloat162* pq0 = (const __nv_bfloat162*)&q0;
        const __nv_bfloat162* pq1 = (const __nv_bfloat162*)&q1;
        const __nv_bfloat162* pk0 = (const __nv_bfloat162*)&k0;
        const __nv_bfloat162* pk1 = (const __nv_bfloat162*)&k1;
#pragma unroll
        for (int e = 0; e < 4; e++) {
            float2 fq0 = __bfloat1622float2(pq0[e]);
            float2 fq1 = __bfloat1622float2(pq1[e]);
            float2 fk0 = __bfloat1622float2(pk0[e]);
            float2 fk1 = __bfloat1622float2(pk1[e]);
            dq += xv[2 * e] * fq0.x + xv[2 * e + 1] * fq0.y
                + xv[8 + 2 * e] * fq1.x + xv[8 + 2 * e + 1] * fq1.y;
            dk += xv[2 * e] * fk0.x + xv[2 * e + 1] * fk0.y
                + xv[8 + 2 * e] * fk1.x + xv[8 + 2 * e + 1] * fk1.y;
        }
#pragma unroll
        for (int o = 16; o; o >>= 1) {
            dq += __shfl_xor_sync(0xffffffffu, dq, o);
            dk += __shfl_xor_sync(0xffffffffu, dk, o);
        }
        float sim = dq * dk;
        ssum += sim;
        if (j == i) ap = sim;
    }
    if (lane == 0) {
        float apm = ssum / (float)cnt;
        float cos_ap  = fminf(fmaxf(ap, 0.f), 1.f);
        float sin_ap  = sqrt_approx(fminf(fmaxf(1.f - cos_ap, 0.f), 1.f));
        float cos_apm = fminf(fmaxf(apm, 0.f), 1.f);
        float sin_apm = sqrt_approx(fminf(fmaxf(1.f - cos_apm, 0.f), 1.f));
        g_cos_apm[i] = cos_apm;
        g_sin_apm[i] = sin_apm;
        float pc = cos_ap * cos_apm - sin_ap * sin_apm;
        float ps = sqrt_approx(fminf(fmaxf(1.f - pc, 0.f), 1.f));
        float phi_pm = pc * K_COSM - ps * K_SINM;
        g_expneg[i] = exp_approx(1.f - phi_pm);
    }
}

// ============== mma.sync bf16 building blocks ==============
__device__ __forceinline__ void ldsm4(uint32_t& r0, uint32_t& r1, uint32_t& r2, uint32_t& r3,
                                      uint32_t addr) {
    asm volatile("ldmatrix.sync.aligned.m8n8.x4.shared.b16 {%0,%1,%2,%3},[%4];\n"
                 : "=r"(r0), "=r"(r1), "=r"(r2), "=r"(r3) : "r"(addr));
}
__device__ __forceinline__ void mma16816(float* c, const uint32_t* a, uint32_t b0, uint32_t b1) {
    asm volatile("mma.sync.aligned.m16n8k16.row.col.f32.bf16.bf16.f32 "
                 "{%0,%1,%2,%3},{%4,%5,%6,%7},{%8,%9},{%0,%1,%2,%3};\n"
                 : "+f"(c[0]), "+f"(c[1]), "+f"(c[2]), "+f"(c[3])
                 : "r"(a[0]), "r"(a[1]), "r"(a[2]), "r"(a[3]), "r"(b0), "r"(b1));
}
__device__ __forceinline__ void cpasync16(uint32_t s, const void* g) {
    asm volatile("cp.async.cg.shared.global [%0],[%1],16;\n" :: "r"(s), "l"(g));
}

#define ROWB 80
#define HALFB (128 * ROWB)
#define STAGEB (256 * ROWB)         // 20480 B
#define NSTAGE 4
#define GEMM_SMEM (NSTAGE * STAGEB) // 81920 B
#define NIT_ 16
#define WAITS(it) do {                                                     \
    if ((it) <= NIT_ - 3)      asm volatile("cp.async.wait_group 2;\n");   \
    else if ((it) == NIT_ - 2) asm volatile("cp.async.wait_group 1;\n");   \
    else                       asm volatile("cp.async.wait_group 0;\n");   \
} while (0)

// ---------------- AAM role (128x128 tile) ----------------
struct TileCtx {
    uint32_t aOff[2], bOff[4];
    uint32_t sa0, sa1, sb0, sb1;
    const __nv_bfloat16 *pa0, *pa1, *pb0, *pb1;
    int wm, wn, lane;
};

__device__ __forceinline__ void tile_init(TileCtx& T, uint32_t sbase, int tid,
                                          const __nv_bfloat16* A, const __nv_bfloat16* Bm,
                                          int bm, int bn) {
    int lane = tid & 31, warp = tid >> 5;
    T.lane = lane;
    T.wm = warp >> 1; T.wn = warp & 1;
    uint32_t sA0 = sbase, sB0 = sbase + HALFB;
    int aRow = T.wm * 32 + (lane & 7) + ((lane >> 3) & 1) * 8;
    int aCol = ((lane >> 4) & 1) * 16;
    int bRow = T.wn * 64 + (lane & 7) + ((lane >> 4) & 1) * 8;
    int bCol = ((lane >> 3) & 1) * 16;
#pragma unroll
    for (int mi = 0; mi < 2; mi++) T.aOff[mi] = sA0 + (uint32_t)((aRow + mi * 16) * ROWB + aCol);
#pragma unroll
    for (int nn = 0; nn < 4; nn++) T.bOff[nn] = sB0 + (uint32_t)((bRow + nn * 16) * ROWB + bCol);
    int c0r = tid >> 2, c0k = tid & 3;
    T.sa0 = sA0 + c0r * ROWB + c0k * 16;
    T.sa1 = sA0 + (c0r + 64) * ROWB + c0k * 16;
    T.sb0 = sB0 + c0r * ROWB + c0k * 16;
    T.sb1 = sB0 + (c0r + 64) * ROWB + c0k * 16;
    T.pa0 = A + (size_t)(bm + c0r) * D_ + c0k * 8;
    T.pa1 = A + (size_t)(bm + c0r + 64) * D_ + c0k * 8;
    T.pb0 = Bm + (size_t)(bn + c0r) * D_ + c0k * 8;
    T.pb1 = Bm + (size_t)(bn + c0r + 64) * D_ + c0k * 8;
}

__device__ __forceinline__ void tile_load(const TileCtx& T, int stage, int k0) {
    uint32_t so = (uint32_t)(stage * STAGEB);
    cpasync16(T.sa0 + so, T.pa0 + k0);
    cpasync16(T.sa1 + so, T.pa1 + k0);
    cpasync16(T.sb0 + so, T.pb0 + k0);
    cpasync16(T.sb1 + so, T.pb1 + k0);
    asm volatile("cp.async.commit_group;\n");
}

__device__ __forceinline__ void tile_compute(const TileCtx& T, int stage, float acc[2][8][4]) {
    uint32_t soff = (uint32_t)(stage * STAGEB);
#pragma unroll
    for (int ks = 0; ks < 2; ks++) {
        uint32_t a[2][4];
        ldsm4(a[0][0], a[0][1], a[0][2], a[0][3], T.aOff[0] + soff + ks * 32);
        ldsm4(a[1][0], a[1][1], a[1][2], a[1][3], T.aOff[1] + soff + ks * 32);
        uint32_t b[8][2];
#pragma unroll
        for (int nn = 0; nn < 4; nn++) {
            uint32_t r0, r1, r2, r3;
            ldsm4(r0, r1, r2, r3, T.bOff[nn] + soff + ks * 32);
            b[2 * nn][0] = r0; b[2 * nn][1] = r1;
            b[2 * nn + 1][0] = r2; b[2 * nn + 1][1] = r3;
        }
#pragma unroll
        for (int mi = 0; mi < 2; mi++)
#pragma unroll
            for (int ni = 0; ni < 8; ni++)
                mma16816(acc[mi][ni], a[mi], b[ni][0], b[ni][1]);
    }
}

// ---------------- QK role (128x64 tile, dual accumulators) ----------------
struct QkCtx {
    uint32_t aOff[2], bqOff[2], bkOff[2];
    uint32_t sa0, sa1, sq, sk;
    const __nv_bfloat16 *pa0, *pa1, *pq, *pk;
    int wm, wn, lane;
};

__device__ __forceinline__ void qk_init(QkCtx& T, uint32_t sbase, int tid,
                                        const __nv_bfloat16* A, const __nv_bfloat16* Bq,
                                        const __nv_bfloat16* Bk, int bm, int bn) {
    int lane = tid & 31, warp = tid >> 5;
    T.lane = lane;
    T.wm = warp >> 1; T.wn = warp & 1;
    uint32_t sA0 = sbase, sQ0 = sbase + HALFB, sK0 = sbase + HALFB + 64 * ROWB;
    int aRow = T.wm * 32 + (lane & 7) + ((lane >> 3) & 1) * 8;
    int aCol = ((lane >> 4) & 1) * 16;
    int bRow = T.wn * 32 + (lane & 7) + ((lane >> 4) & 1) * 8;
    int bCol = ((lane >> 3) & 1) * 16;
#pragma unroll
    for (int mi = 0; mi < 2; mi++) T.aOff[mi] = sA0 + (uint32_t)((aRow + mi * 16) * ROWB + aCol);
#pragma unroll
    for (int nn = 0; nn < 2; nn++) {
        T.bqOff[nn] = sQ0 + (uint32_t)((bRow + nn * 16) * ROWB + bCol);
        T.bkOff[nn] = sK0 + (uint32_t)((bRow + nn * 16) * ROWB + bCol);
    }
    int c0r = tid >> 2, c0k = tid & 3;
    T.sa0 = sA0 + c0r * ROWB + c0k * 16;
    T.sa1 = sA0 + (c0r + 64) * ROWB + c0k * 16;
    T.sq  = sQ0 + c0r * ROWB + c0k * 16;
    T.sk  = sK0 + c0r * ROWB + c0k * 16;
    T.pa0 = A  + (size_t)(bm + c0r) * D_ + c0k * 8;
    T.pa1 = A  + (size_t)(bm + c0r + 64) * D_ + c0k * 8;
    T.pq  = Bq + (size_t)(bn + c0r) * D_ + c0k * 8;
    T.pk  = Bk + (size_t)(bn + c0r) * D_ + c0k * 8;
}

__device__ __forceinline__ void qk_load(const QkCtx& T, int stage, int k0) {
    uint32_t so = (uint32_t)(stage * STAGEB);
    cpasync16(T.sa0 + so, T.pa0 + k0);
    cpasync16(T.sa1 + so, T.pa1 + k0);
    cpasync16(T.sq  + so, T.pq  + k0);
    cpasync16(T.sk  + so, T.pk  + k0);
    asm volatile("cp.async.commit_group;\n");
}

__device__ __forceinline__ void qk_compute(const QkCtx& T, int stage,
                                           float aq[2][4][4], float ak[2][4][4]) {
    uint32_t soff = (uint32_t)(stage * STAGEB);
#pragma unroll
    for (int ks = 0; ks < 2; ks++) {
        uint32_t a[2][4];
        ldsm4(a[0][0], a[0][1], a[0][2], a[0][3], T.aOff[0] + soff + ks * 32);
        ldsm4(a[1][0], a[1][1], a[1][2], a[1][3], T.aOff[1] + soff + ks * 32);
        uint32_t bq[4][2], bk[4][2];
#pragma unroll
        for (int nn = 0; nn < 2; nn++) {
            uint32_t r0, r1, r2, r3;
            ldsm4(r0, r1, r2, r3, T.bqOff[nn] + soff + ks * 32);
            bq[2 * nn][0] = r0; bq[2 * nn][1] = r1;
            bq[2 * nn + 1][0] = r2; bq[2 * nn + 1][1] = r3;
            ldsm4(r0, r1, r2, r3, T.bkOff[nn] + soff + ks * 32);
            bk[2 * nn][0] = r0; bk[2 * nn][1] = r1;
            bk[2 * nn + 1][0] = r2; bk[2 * nn + 1][1] = r3;
        }
#pragma unroll
        for (int mi = 0; mi < 2; mi++)
#pragma unroll
            for (int ni = 0; ni < 4; ni++) {
                mma16816(aq[mi][ni], a[mi], bq[ni][0], bq[ni][1]);
                mma16816(ak[mi][ni], a[mi], bk[ni][0], bk[ni][1]);
            }
    }
}

// ---------- nm term ----------
__device__ __forceinline__ float nm_term(float sim, float capm, float sapm) {
    float ca = fminf(fmaxf(sim, 0.f), 1.f);
    float sa = sqrt_approx(fminf(fmaxf(1.f - ca, 0.f), 1.f));
    float ss = sa * capm + ca * sapm;
    float cc = sqrt_approx(fminf(fmaxf(1.f - ss, 0.f), 1.f));
    return exp_approx(ss * K_COSM - cc * K_SINM);
}

// ============== mega kernel: AAM blocks + QK blocks, atomic row accumulation ==============
__global__ void __launch_bounds__(256, 2)
mega_gemm(const __nv_bfloat16* __restrict__ Axh, const __nv_bfloat16* __restrict__ Bw,
          const __nv_bfloat16* __restrict__ Bwm, const __nv_bfloat16* __restrict__ Bwk,
          const int* __restrict__ label) {
    extern __shared__ __align__(16) char smem[];
    uint32_t sbase = (uint32_t)__cvta_generic_to_shared(smem);
    int tid = threadIdx.x;

    if (blockIdx.x < NAAMBLK) {
        int bx = blockIdx.x % NTC, by = blockIdx.x / NTC;
        int bm = by * 128, bn = bx * 128;
        TileCtx T;
        tile_init(T, sbase, tid, Axh, Bw, bm, bn);
        float acc[2][8][4];
#pragma unroll
        for (int mi = 0; mi < 2; mi++)
#pragma unroll
            for (int ni = 0; ni < 8; ni++)
#pragma unroll
                for (int e = 0; e < 4; e++) acc[mi][ni][e] = 0.f;

        tile_load(T, 0, 0);
        tile_load(T, 1, 32);
        tile_load(T, 2, 64);
#pragma unroll
        for (int it = 0; it < NIT_; it++) {
            WAITS(it);
            __syncthreads();
            tile_compute(T, it & 3, acc);
            if (it + 3 < NIT_) tile_load(T, (it + 3) & 3, (it + 3) * 32);
        }

        int lane = T.lane;
        int colbase = bn + T.wn * 64 + (lane & 3) * 2;
#pragma unroll
        for (int mi = 0; mi < 2; mi++) {
#pragma unroll
            for (int h = 0; h < 2; h++) {
                int row = bm + T.wm * 32 + mi * 16 + (lane >> 2) + h * 8;
                int lab = label[row];
                float se = 0.f, sc = 0.f, cy = 0.f;
#pragma unroll
                for (int ni = 0; ni < 8; ni++) {
                    int col = colbase + ni * 8;
                    float v0 = acc[mi][ni][h * 2 + 0];
                    float v1 = acc[mi][ni][h * 2 + 1];
                    if (col < C_) {
                        sc += v0;
                        se += exp_approx(K_S * (v0 - 1.f));
                        if (col == lab) cy = v0;
                    }
                    if (col + 1 < C_) {
                        sc += v1;
                        se += exp_approx(K_S * (v1 - 1.f));
                        if (col + 1 == lab) cy = v1;
                    }
                }
                se += __shfl_xor_sync(0xffffffffu, se, 1);
                se += __shfl_xor_sync(0xffffffffu, se, 2);
                sc += __shfl_xor_sync(0xffffffffu, sc, 1);
                sc += __shfl_xor_sync(0xffffffffu, sc, 2);
                cy += __shfl_xor_sync(0xffffffffu, cy, 1);
                cy += __shfl_xor_sync(0xffffffffu, cy, 2);
                if ((lane & 3) == 0) {
                    atomicAdd(&g_rexp[row], se);
                    atomicAdd(&g_rsum[row], sc);
                    int cb = bn + T.wn * 64;
                    if (lab >= cb && lab < cb + 64) g_cy[row] = cy;
                }
            }
        }
    } else {
        int idx = blockIdx.x - NAAMBLK;
        int cn = idx % NQCT, rm = idx / NQCT;
        int bm = rm * 128, bn = cn * 64;
        QkCtx T;
        qk_init(T, sbase, tid, Axh, Bwm, Bwk, bm, bn);
        float aq[2][4][4], ak[2][4][4];
#pragma unroll
        for (int mi = 0; mi < 2; mi++)
#pragma unroll
            for (int ni = 0; ni < 4; ni++)
#pragma unroll
                for (int e = 0; e < 4; e++) { aq[mi][ni][e] = 0.f; ak[mi][ni][e] = 0.f; }

        qk_load(T, 0, 0);
        qk_load(T, 1, 32);
        qk_load(T, 2, 64);
#pragma unroll
        for (int it = 0; it < NIT_; it++) {
            WAITS(it);
            __syncthreads();
            qk_compute(T, it & 3, aq, ak);
            if (it + 3 < NIT_) qk_load(T, (it + 3) & 3, (it + 3) * 32);
        }

        __syncthreads();
        float* s_capm = (float*)smem;
        float* s_sapm = s_capm + 64;
        int*   s_lcol = (int*)(s_sapm + 64);
        int*   s_lrow = s_lcol + 64;
        if (tid < 64) {
            s_capm[tid] = g_cos_apm[bn + tid];
            s_sapm[tid] = g_sin_apm[bn + tid];
            s_lcol[tid] = label[bn + tid];
        } else if (tid < 192) {
            s_lrow[tid - 64] = label[bm + tid - 64];
        }
        __syncthreads();

        int lane = T.lane;
        int colloc0 = T.wn * 32 + (lane & 3) * 2;
#pragma unroll
        for (int mi = 0; mi < 2; mi++) {
#pragma unroll
            for (int h = 0; h < 2; h++) {
                int rloc = T.wm * 32 + mi * 16 + (lane >> 2) + h * 8;
                int row = bm + rloc;
                int lrow = s_lrow[rloc];
                float s = 0.f;
#pragma unroll
                for (int ni = 0; ni < 4; ni++) {
                    int cl = colloc0 + ni * 8;
                    float s0 = aq[mi][ni][h * 2 + 0] * ak[mi][ni][h * 2 + 0];
                    float s1 = aq[mi][ni][h * 2 + 1] * ak[mi][ni][h * 2 + 1];
                    if (s_lcol[cl] != lrow)     s += nm_term(s0, s_capm[cl], s_sapm[cl]);
                    if (s_lcol[cl + 1] != lrow) s += nm_term(s1, s_capm[cl + 1], s_sapm[cl + 1]);
                }
                s += __shfl_xor_sync(0xffffffffu, s, 1);
                s += __shfl_xor_sync(0xffffffffu, s, 2);
                if ((lane & 3) == 0)
                    atomicAdd(&g_nmp[row], s);
            }
        }
    }
}

// ---------- final combine: 8 blocks, row math parallel, last-block finish ----------
__global__ void __launch_bounds__(256)
final_combine(float* __restrict__ out) {
    int j = blockIdx.x * 256 + threadIdx.x;   // one row per thread
    float se = g_rexp[j];
    float sc = g_rsum[j];
    float cyv = g_cy[j];
    float sine = sqrt_approx(fminf(fmaxf(1.f - cyv * cyv, 0.f), 1.f));
    float phi = cyv * K_COSM - sine * K_SINM;
    phi = (cyv - K_TH > 0.f) ? phi : (cyv - K_MM);
    float oy = K_S * phi, ocy = K_S * cyv;
    float sout = K_S * sc + (oy - ocy);
    se += exp_approx(oy - K_S) - exp_approx(ocy - K_S);
    float lse = K_S + log_approx(se);
    float sa = (1.f - K_EPS) * (oy - lse) + (K_EPS / C_) * sout - K_EPS * lse;
    float sn = g_expneg[j];
    float sm = g_nmp[j];
    sa = block_sum_all(sa);
    sn = block_sum_all(sn);
    sm = block_sum_all(sm);
    if (threadIdx.x == 0) {
        atomicAdd(&g_acc[0], sa);
        atomicAdd(&g_acc[1], sn);
        atomicAdd(&g_acc[2], sm);
        __threadfence();
        unsigned t = atomicAdd(&g_ticket, 1u);
        if (t == NFINAL - 1) {
            float fsa = g_acc[0], fsn = g_acc[1], fsm = g_acc[2];
            float aam_loss = -fsa / (float)B_;
            float z = logf(fsm) + logf(fsn);
            float cc = fmaxf(z, 0.f) + log1pf(expf(-fabsf(z)));
            out[0] = aam_loss + cc;
        }
    }
}

// ---------- launcher ----------
extern "C" void kernel_launch(void* const* d_in, const int* in_sizes, int n_in,
                              void* d_out, int out_size) {
    const float* x        = (const float*)d_in[0];
    const int*   label    = (const int*)d_in[1];
    const float* weight   = (const float*)d_in[2];
    const float* weight_m = (const float*)d_in[3];
    const float* weight_n = (const float*)d_in[4];
    float* out = (float*)d_out;

    __nv_bfloat16 *p_xh, *p_wh, *p_wmh, *p_wkh;
    cudaGetSymbolAddress((void**)&p_xh,  g_xh);
    cudaGetSymbolAddress((void**)&p_wh,  g_wh);
    cudaGetSymbolAddress((void**)&p_wmh, g_wmh);
    cudaGetSymbolAddress((void**)&p_wkh, g_wkh);

    cudaFuncSetAttribute(mega_gemm, cudaFuncAttributeMaxDynamicSharedMemorySize, GEMM_SMEM);

    prep_kernel<<<PREP_ZBASE + 49, 128>>>(x, weight, weight_m, weight_n, label);
    apm_pairs_kernel<<<B_ / 8, 256>>>(label);
    mega_gemm<<<NAAMBLK + NQKBLK, 256, GEMM_SMEM>>>(p_xh, p_wh, p_wmh, p_wkh, label);
    final_combine<<<NFINAL, 256>>>(out);
}